// round 1
// baseline (speedup 1.0000x reference)
#include <cuda_runtime.h>

#define NM 100000           // movies
#define NU 50000            // users
#define NN 150000           // total nodes
#define NE 500000           // edges
#define D1 128              // emb dim
#define D2 256              // hidden dim

// ---------------- scratch (device globals; no allocation allowed) ----------
__device__ float g_agg1[(size_t)NN * D1];   // 76.8 MB
__device__ float g_h[(size_t)NN * D2];      // 153.6 MB
__device__ float g_agg2[(size_t)NN * D2];   // 153.6 MB
__device__ int   g_deg[NN];
__device__ int   g_off[NN + 1];
__device__ int   g_pos[NN];
__device__ int   g_srcs[NE];
__device__ int   g_bsum[256];
__device__ int   g_is64;

// ---------------- edge index access (int32 vs int64 at runtime) ------------
__device__ __forceinline__ int edge_idx(const void* ei, int which, int e) {
    if (g_is64) {
        const long long* p = (const long long*)ei;
        return (int)p[(size_t)which * NE + e];
    } else {
        const int* p = (const int*)ei;
        return p[(size_t)which * NE + e];
    }
}

__global__ void k_detect(const void* ei) {
    // If data is really int64, every int64 word is a valid node id.
    // If it's int32, reinterpreted pairs are ~always >= 2^32.
    const long long* p = (const long long*)ei;
    int bad = 0;
    for (int i = threadIdx.x; i < 2048; i += blockDim.x) {
        long long v = p[i];
        if (v < 0 || v >= NN) bad = 1;
    }
    bad = __syncthreads_or(bad);
    if (threadIdx.x == 0) g_is64 = bad ? 0 : 1;
}

// ---------------- degree histogram ------------------------------------------
__global__ void k_zero() {
    int i = blockIdx.x * blockDim.x + threadIdx.x;
    if (i < NN) g_deg[i] = 0;
}

__global__ void k_count(const void* ei) {
    int e = blockIdx.x * blockDim.x + threadIdx.x;
    if (e < NE) atomicAdd(&g_deg[edge_idx(ei, 1, e)], 1);
}

// ---------------- exclusive scan (3 kernels) --------------------------------
__global__ void k_scan1() {
    __shared__ int s[1024];
    int i = blockIdx.x * 1024 + threadIdx.x;
    int v = (i < NN) ? g_deg[i] : 0;
    s[threadIdx.x] = v;
    __syncthreads();
#pragma unroll
    for (int off = 1; off < 1024; off <<= 1) {
        int t = (threadIdx.x >= off) ? s[threadIdx.x - off] : 0;
        __syncthreads();
        s[threadIdx.x] += t;
        __syncthreads();
    }
    if (i < NN) g_off[i] = s[threadIdx.x] - v;   // exclusive
    if (threadIdx.x == 1023) g_bsum[blockIdx.x] = s[1023];
}

__global__ void k_scan2() {
    __shared__ int s[256];
    const int NB = (NN + 1023) / 1024;   // 147
    int v = (threadIdx.x < NB) ? g_bsum[threadIdx.x] : 0;
    s[threadIdx.x] = v;
    __syncthreads();
#pragma unroll
    for (int off = 1; off < 256; off <<= 1) {
        int t = (threadIdx.x >= off) ? s[threadIdx.x - off] : 0;
        __syncthreads();
        s[threadIdx.x] += t;
        __syncthreads();
    }
    if (threadIdx.x < NB) g_bsum[threadIdx.x] = s[threadIdx.x] - v;  // exclusive
}

__global__ void k_scan3() {
    int i = blockIdx.x * blockDim.x + threadIdx.x;
    if (i < NN) {
        int val = g_off[i] + g_bsum[i >> 10];
        g_off[i] = val;
        g_pos[i] = val;
    }
    if (i == 0) g_off[NN] = NE;
}

// ---------------- bucket edges by dst ---------------------------------------
__global__ void k_bucket(const void* ei) {
    int e = blockIdx.x * blockDim.x + threadIdx.x;
    if (e < NE) {
        int d = edge_idx(ei, 1, e);
        int p = atomicAdd(&g_pos[d], 1);
        g_srcs[p] = edge_idx(ei, 0, e);
    }
}

// ---------------- layer-1 aggregation: mean of x[src] per dst (D=128) -------
__global__ void k_agg1(const float* __restrict__ movie, const float* __restrict__ user) {
    int warp = threadIdx.x >> 5;
    int lane = threadIdx.x & 31;
    int node = blockIdx.x * 8 + warp;
    if (node >= NN) return;
    int beg = g_off[node], end = g_off[node + 1];
    float4 acc = make_float4(0.f, 0.f, 0.f, 0.f);
    for (int e = beg; e < end; e++) {
        int s = g_srcs[e];
        const float4* row = (s < NM)
            ? (const float4*)(movie + (size_t)s * D1)
            : (const float4*)(user + (size_t)(s - NM) * D1);
        float4 v = row[lane];
        acc.x += v.x; acc.y += v.y; acc.z += v.z; acc.w += v.w;
    }
    int cnt = end - beg;
    float inv = 1.0f / (float)(cnt > 0 ? cnt : 1);
    acc.x *= inv; acc.y *= inv; acc.z *= inv; acc.w *= inv;
    ((float4*)(g_agg1 + (size_t)node * D1))[lane] = acc;
}

// ---------------- GEMM1: h = relu([agg1 | x] @ [W_l1 ; W_r1] + b_l1) --------
// A[N,256] virtual, B[256,256], C[N,256]. BM=64, BN=256, BK=16. 256 thr, 8x8.
__global__ void __launch_bounds__(256) k_gemm1(
    const float* __restrict__ movie, const float* __restrict__ user,
    const float* __restrict__ Wl, const float* __restrict__ Wr,
    const float* __restrict__ bias)
{
    __shared__ float As[16][64];
    __shared__ float Bs[16][256];
    int tid = threadIdx.x;
    int row0 = blockIdx.x * 64;
    int tx = tid & 31, ty = tid >> 5;
    float acc[8][8];
#pragma unroll
    for (int i = 0; i < 8; i++)
#pragma unroll
        for (int j = 0; j < 8; j++) acc[i][j] = 0.f;

    for (int k0 = 0; k0 < 256; k0 += 16) {
        // As: 64 nodes x 16 k, transposed load (each thread: 4 consecutive k)
        {
            int linear = tid * 4;
            int m = linear >> 4;
            int kk = linear & 15;
            int grow = row0 + m;
            float4 v = make_float4(0.f, 0.f, 0.f, 0.f);
            if (grow < NN) {
                int k = k0 + kk;
                if (k < 128) {
                    v = *(const float4*)(g_agg1 + (size_t)grow * D1 + k);
                } else {
                    int kx = k - 128;
                    const float* xr = (grow < NM)
                        ? movie + (size_t)grow * D1
                        : user + (size_t)(grow - NM) * D1;
                    v = *(const float4*)(xr + kx);
                }
            }
            As[kk + 0][m] = v.x;
            As[kk + 1][m] = v.y;
            As[kk + 2][m] = v.z;
            As[kk + 3][m] = v.w;
        }
        // Bs: 16 k x 256 j
#pragma unroll
        for (int i = 0; i < 4; i++) {
            int f = tid + i * 256;      // float4 id 0..1023
            int r = f >> 6;
            int c4 = f & 63;
            int k = k0 + r;
            const float* Brow = (k < 128) ? Wl + (size_t)k * 256
                                          : Wr + (size_t)(k - 128) * 256;
            *(float4*)&Bs[r][c4 * 4] = *(const float4*)(Brow + c4 * 4);
        }
        __syncthreads();
#pragma unroll
        for (int kk = 0; kk < 16; kk++) {
            float a[8], b[8];
            *(float4*)(a)     = *(float4*)&As[kk][ty * 8];
            *(float4*)(a + 4) = *(float4*)&As[kk][ty * 8 + 4];
            *(float4*)(b)     = *(float4*)&Bs[kk][tx * 8];
            *(float4*)(b + 4) = *(float4*)&Bs[kk][tx * 8 + 4];
#pragma unroll
            for (int i = 0; i < 8; i++)
#pragma unroll
                for (int j = 0; j < 8; j++) acc[i][j] += a[i] * b[j];
        }
        __syncthreads();
    }
    // epilogue: bias + relu
    float bv[8];
    *(float4*)(bv)     = *(const float4*)(bias + tx * 8);
    *(float4*)(bv + 4) = *(const float4*)(bias + tx * 8 + 4);
#pragma unroll
    for (int i = 0; i < 8; i++) {
        int m = row0 + ty * 8 + i;
        if (m >= NN) break;
        float* out = g_h + (size_t)m * D2 + tx * 8;
        float4 o1, o2;
        o1.x = fmaxf(acc[i][0] + bv[0], 0.f);
        o1.y = fmaxf(acc[i][1] + bv[1], 0.f);
        o1.z = fmaxf(acc[i][2] + bv[2], 0.f);
        o1.w = fmaxf(acc[i][3] + bv[3], 0.f);
        o2.x = fmaxf(acc[i][4] + bv[4], 0.f);
        o2.y = fmaxf(acc[i][5] + bv[5], 0.f);
        o2.z = fmaxf(acc[i][6] + bv[6], 0.f);
        o2.w = fmaxf(acc[i][7] + bv[7], 0.f);
        *(float4*)(out)     = o1;
        *(float4*)(out + 4) = o2;
    }
}

// ---------------- layer-2 aggregation: mean of h[src] per dst (D=256) -------
__global__ void k_agg2() {
    int warp = threadIdx.x >> 5;
    int lane = threadIdx.x & 31;
    int node = blockIdx.x * 8 + warp;
    if (node >= NN) return;
    int beg = g_off[node], end = g_off[node + 1];
    float4 a0 = make_float4(0.f, 0.f, 0.f, 0.f);
    float4 a1 = make_float4(0.f, 0.f, 0.f, 0.f);
    for (int e = beg; e < end; e++) {
        int s = g_srcs[e];
        const float4* row = (const float4*)(g_h + (size_t)s * D2);
        float4 v0 = row[lane];
        float4 v1 = row[lane + 32];
        a0.x += v0.x; a0.y += v0.y; a0.z += v0.z; a0.w += v0.w;
        a1.x += v1.x; a1.y += v1.y; a1.z += v1.z; a1.w += v1.w;
    }
    int cnt = end - beg;
    float inv = 1.0f / (float)(cnt > 0 ? cnt : 1);
    a0.x *= inv; a0.y *= inv; a0.z *= inv; a0.w *= inv;
    a1.x *= inv; a1.y *= inv; a1.z *= inv; a1.w *= inv;
    float4* out = (float4*)(g_agg2 + (size_t)node * D2);
    out[lane]      = a0;
    out[lane + 32] = a1;
}

// ---------------- GEMM2: refined = [agg2 | h] @ [W_l2 ; W_r2] + b_l2 --------
// A[N,512] virtual, B[512,128], C[N,128]. BM=64, BN=128, BK=16. 256 thr, 8x4.
__global__ void __launch_bounds__(256) k_gemm2(
    const float* __restrict__ Wl, const float* __restrict__ Wr,
    const float* __restrict__ bias, float* __restrict__ refined)
{
    __shared__ float As[16][64];
    __shared__ float Bs[16][128];
    int tid = threadIdx.x;
    int row0 = blockIdx.x * 64;
    int tx = tid & 31, ty = tid >> 5;
    float acc[8][4];
#pragma unroll
    for (int i = 0; i < 8; i++)
#pragma unroll
        for (int j = 0; j < 4; j++) acc[i][j] = 0.f;

    for (int k0 = 0; k0 < 512; k0 += 16) {
        // As: 64 nodes x 16 k transposed
        {
            int linear = tid * 4;
            int m = linear >> 4;
            int kk = linear & 15;
            int grow = row0 + m;
            float4 v = make_float4(0.f, 0.f, 0.f, 0.f);
            if (grow < NN) {
                int k = k0 + kk;
                const float* src = (k < 256)
                    ? g_agg2 + (size_t)grow * D2 + k
                    : g_h + (size_t)grow * D2 + (k - 256);
                v = *(const float4*)src;
            }
            As[kk + 0][m] = v.x;
            As[kk + 1][m] = v.y;
            As[kk + 2][m] = v.z;
            As[kk + 3][m] = v.w;
        }
        // Bs: 16 k x 128 j  (512 float4 / 256 threads = 2 each)
#pragma unroll
        for (int i = 0; i < 2; i++) {
            int f = tid + i * 256;
            int r = f >> 5;
            int c4 = f & 31;
            int k = k0 + r;
            const float* Brow = (k < 256) ? Wl + (size_t)k * 128
                                          : Wr + (size_t)(k - 256) * 128;
            *(float4*)&Bs[r][c4 * 4] = *(const float4*)(Brow + c4 * 4);
        }
        __syncthreads();
#pragma unroll
        for (int kk = 0; kk < 16; kk++) {
            float a[8], b[4];
            *(float4*)(a)     = *(float4*)&As[kk][ty * 8];
            *(float4*)(a + 4) = *(float4*)&As[kk][ty * 8 + 4];
            *(float4*)(b)     = *(float4*)&Bs[kk][tx * 4];
#pragma unroll
            for (int i = 0; i < 8; i++)
#pragma unroll
                for (int j = 0; j < 4; j++) acc[i][j] += a[i] * b[j];
        }
        __syncthreads();
    }
    float4 bv = *(const float4*)(bias + tx * 4);
#pragma unroll
    for (int i = 0; i < 8; i++) {
        int m = row0 + ty * 8 + i;
        if (m >= NN) break;
        float4 o;
        o.x = acc[i][0] + bv.x;
        o.y = acc[i][1] + bv.y;
        o.z = acc[i][2] + bv.z;
        o.w = acc[i][3] + bv.w;
        *(float4*)(refined + (size_t)m * D1 + tx * 4) = o;
    }
}

// ---------------- edge scoring: out[e] = refined[src] . refined[dst] --------
__global__ void k_score(const void* ei, const float* __restrict__ refined,
                        float* __restrict__ out)
{
    int warp = threadIdx.x >> 5;
    int lane = threadIdx.x & 31;
    int e = blockIdx.x * 8 + warp;
    if (e >= NE) return;
    int s = edge_idx(ei, 0, e);
    int d = edge_idx(ei, 1, e);
    float4 va = ((const float4*)(refined + (size_t)s * D1))[lane];
    float4 vb = ((const float4*)(refined + (size_t)d * D1))[lane];
    float t = va.x * vb.x + va.y * vb.y + va.z * vb.z + va.w * vb.w;
#pragma unroll
    for (int o = 16; o > 0; o >>= 1) t += __shfl_xor_sync(0xFFFFFFFFu, t, o);
    if (lane == 0) out[e] = t;
}

// ---------------- launch -----------------------------------------------------
extern "C" void kernel_launch(void* const* d_in, const int* in_sizes, int n_in,
                              void* d_out, int out_size)
{
    const void*  ei    = d_in[0];
    // d_in[1] = edge_attr (unused by reference)
    const float* movie = (const float*)d_in[2];
    const float* user  = (const float*)d_in[3];
    const float* Wl1   = (const float*)d_in[4];
    const float* bl1   = (const float*)d_in[5];
    const float* Wr1   = (const float*)d_in[6];
    const float* Wl2   = (const float*)d_in[7];
    const float* bl2   = (const float*)d_in[8];
    const float* Wr2   = (const float*)d_in[9];

    float* out     = (float*)d_out;       // [NE] predicted ratings
    float* refined = out + NE;            // [NN * D1]

    k_detect<<<1, 256>>>(ei);
    k_zero<<<(NN + 255) / 256, 256>>>();
    k_count<<<(NE + 255) / 256, 256>>>(ei);
    k_scan1<<<(NN + 1023) / 1024, 1024>>>();
    k_scan2<<<1, 256>>>();
    k_scan3<<<(NN + 255) / 256, 256>>>();
    k_bucket<<<(NE + 255) / 256, 256>>>(ei);
    k_agg1<<<NN / 8, 256>>>(movie, user);
    k_gemm1<<<(NN + 63) / 64, 256>>>(movie, user, Wl1, Wr1, bl1);
    k_agg2<<<NN / 8, 256>>>();
    k_gemm2<<<(NN + 63) / 64, 256>>>(Wl2, Wr2, bl2, refined);
    k_score<<<(NE + 7) / 8, 256>>>(ei, refined, out);
}

// round 4
// speedup vs baseline: 1.4164x; 1.4164x over previous
#include <cuda_runtime.h>
#include <cuda_bf16.h>
#include <cstdint>
#include <cstddef>

#define NM 100000           // movies
#define NU 50000            // users
#define NN 150000           // total nodes
#define NE 500000           // edges
#define D1 128              // emb dim
#define D2 256              // hidden dim

// ---------------- scratch (device globals; no allocation allowed) ----------
__device__ float g_agg1[(size_t)NN * D1];   // 76.8 MB
__device__ float g_h[(size_t)NN * D2];      // 153.6 MB
__device__ float g_agg2[(size_t)NN * D2];   // 153.6 MB
__device__ int   g_deg[NN];
__device__ int   g_off[NN + 1];
__device__ int   g_pos[NN];
__device__ int   g_srcs[NE];
__device__ int   g_bsum[256];
__device__ int   g_is64;

// ---------------- edge index access (int32 vs int64 at runtime) ------------
__device__ __forceinline__ int edge_idx(const void* ei, int which, int e) {
    if (g_is64) {
        const long long* p = (const long long*)ei;
        return (int)p[(size_t)which * NE + e];
    } else {
        const int* p = (const int*)ei;
        return p[(size_t)which * NE + e];
    }
}

__global__ void k_detect(const void* ei) {
    const long long* p = (const long long*)ei;
    int bad = 0;
    for (int i = threadIdx.x; i < 2048; i += blockDim.x) {
        long long v = p[i];
        if (v < 0 || v >= NN) bad = 1;
    }
    bad = __syncthreads_or(bad);
    if (threadIdx.x == 0) g_is64 = bad ? 0 : 1;
}

// ---------------- degree histogram ------------------------------------------
__global__ void k_zero() {
    int i = blockIdx.x * blockDim.x + threadIdx.x;
    if (i < NN) g_deg[i] = 0;
}

__global__ void k_count(const void* ei) {
    int e = blockIdx.x * blockDim.x + threadIdx.x;
    if (e < NE) atomicAdd(&g_deg[edge_idx(ei, 1, e)], 1);
}

// ---------------- exclusive scan (3 kernels) --------------------------------
__global__ void k_scan1() {
    __shared__ int s[1024];
    int i = blockIdx.x * 1024 + threadIdx.x;
    int v = (i < NN) ? g_deg[i] : 0;
    s[threadIdx.x] = v;
    __syncthreads();
#pragma unroll
    for (int off = 1; off < 1024; off <<= 1) {
        int t = (threadIdx.x >= off) ? s[threadIdx.x - off] : 0;
        __syncthreads();
        s[threadIdx.x] += t;
        __syncthreads();
    }
    if (i < NN) g_off[i] = s[threadIdx.x] - v;   // exclusive
    if (threadIdx.x == 1023) g_bsum[blockIdx.x] = s[1023];
}

__global__ void k_scan2() {
    __shared__ int s[256];
    const int NB = (NN + 1023) / 1024;   // 147
    int v = (threadIdx.x < NB) ? g_bsum[threadIdx.x] : 0;
    s[threadIdx.x] = v;
    __syncthreads();
#pragma unroll
    for (int off = 1; off < 256; off <<= 1) {
        int t = (threadIdx.x >= off) ? s[threadIdx.x - off] : 0;
        __syncthreads();
        s[threadIdx.x] += t;
        __syncthreads();
    }
    if (threadIdx.x < NB) g_bsum[threadIdx.x] = s[threadIdx.x] - v;  // exclusive
}

__global__ void k_scan3() {
    int i = blockIdx.x * blockDim.x + threadIdx.x;
    if (i < NN) {
        int val = g_off[i] + g_bsum[i >> 10];
        g_off[i] = val;
        g_pos[i] = val;
    }
    if (i == 0) g_off[NN] = NE;
}

// ---------------- bucket edges by dst ---------------------------------------
__global__ void k_bucket(const void* ei) {
    int e = blockIdx.x * blockDim.x + threadIdx.x;
    if (e < NE) {
        int d = edge_idx(ei, 1, e);
        int p = atomicAdd(&g_pos[d], 1);
        g_srcs[p] = edge_idx(ei, 0, e);
    }
}

// ---------------- layer-1 aggregation: mean of x[src] per dst (D=128) -------
__global__ void k_agg1(const float* __restrict__ movie, const float* __restrict__ user) {
    int warp = threadIdx.x >> 5;
    int lane = threadIdx.x & 31;
    int node = blockIdx.x * 8 + warp;
    if (node >= NN) return;
    int beg = g_off[node], end = g_off[node + 1];
    float4 acc = make_float4(0.f, 0.f, 0.f, 0.f);
    for (int e = beg; e < end; e++) {
        int s = g_srcs[e];
        const float4* row = (s < NM)
            ? (const float4*)(movie + (size_t)s * D1)
            : (const float4*)(user + (size_t)(s - NM) * D1);
        float4 v = row[lane];
        acc.x += v.x; acc.y += v.y; acc.z += v.z; acc.w += v.w;
    }
    int cnt = end - beg;
    float inv = 1.0f / (float)(cnt > 0 ? cnt : 1);
    acc.x *= inv; acc.y *= inv; acc.z *= inv; acc.w *= inv;
    ((float4*)(g_agg1 + (size_t)node * D1))[lane] = acc;
}

// ---------------- layer-2 aggregation: mean of h[src] per dst (D=256) -------
__global__ void k_agg2() {
    int warp = threadIdx.x >> 5;
    int lane = threadIdx.x & 31;
    int node = blockIdx.x * 8 + warp;
    if (node >= NN) return;
    int beg = g_off[node], end = g_off[node + 1];
    float4 a0 = make_float4(0.f, 0.f, 0.f, 0.f);
    float4 a1 = make_float4(0.f, 0.f, 0.f, 0.f);
    for (int e = beg; e < end; e++) {
        int s = g_srcs[e];
        const float4* row = (const float4*)(g_h + (size_t)s * D2);
        float4 v0 = row[lane];
        float4 v1 = row[lane + 32];
        a0.x += v0.x; a0.y += v0.y; a0.z += v0.z; a0.w += v0.w;
        a1.x += v1.x; a1.y += v1.y; a1.z += v1.z; a1.w += v1.w;
    }
    int cnt = end - beg;
    float inv = 1.0f / (float)(cnt > 0 ? cnt : 1);
    a0.x *= inv; a0.y *= inv; a0.z *= inv; a0.w *= inv;
    a1.x *= inv; a1.y *= inv; a1.z *= inv; a1.w *= inv;
    float4* out = (float4*)(g_agg2 + (size_t)node * D2);
    out[lane]      = a0;
    out[lane + 32] = a1;
}

// ---------------- tensor-core GEMM (bf16 3-way split = fp32-accurate) -------
// LAYER 1: A = [agg1 | x]   [NN,256], B = [Wl1;Wr1] [256,256], out g_h (relu)
// LAYER 2: A = [agg2 | h]   [NN,512], B = [Wl2;Wr2] [512,128], out refined
// BM=128, BN=128, BK=32, 256 threads, 8 warps of 64x32 tiles, mma m16n8k16.

__device__ __forceinline__ void ldsm4(uint32_t* r, uint32_t a) {
    asm volatile("ldmatrix.sync.aligned.m8n8.x4.shared.b16 {%0,%1,%2,%3}, [%4];"
                 : "=r"(r[0]), "=r"(r[1]), "=r"(r[2]), "=r"(r[3]) : "r"(a));
}
__device__ __forceinline__ void ldsm2t(uint32_t* r, uint32_t a) {
    asm volatile("ldmatrix.sync.aligned.m8n8.x2.trans.shared.b16 {%0,%1}, [%2];"
                 : "=r"(r[0]), "=r"(r[1]) : "r"(a));
}
__device__ __forceinline__ void mma_bf16(float* c, const uint32_t* a, const uint32_t* b) {
    asm volatile(
        "mma.sync.aligned.m16n8k16.row.col.f32.bf16.bf16.f32 "
        "{%0,%1,%2,%3},{%4,%5,%6,%7},{%8,%9},{%0,%1,%2,%3};"
        : "+f"(c[0]), "+f"(c[1]), "+f"(c[2]), "+f"(c[3])
        : "r"(a[0]), "r"(a[1]), "r"(a[2]), "r"(a[3]), "r"(b[0]), "r"(b[1]));
}
__device__ __forceinline__ uint32_t pk(__nv_bfloat16 a, __nv_bfloat16 b) {
    return (uint32_t)__bfloat16_as_ushort(a) |
           ((uint32_t)__bfloat16_as_ushort(b) << 16);
}

template <int LAYER>
__global__ void __launch_bounds__(256) k_gemm_tc(
    const float* __restrict__ movie, const float* __restrict__ user,
    const float* __restrict__ Wl, const float* __restrict__ Wr,
    const float* __restrict__ bias, float* __restrict__ outp)
{
    constexpr int KTOT = (LAYER == 1) ? 256 : 512;
    constexpr int NOUT = (LAYER == 1) ? 256 : 128;   // C row stride
    constexpr int KA   = (LAYER == 1) ? 128 : 256;   // A region split point

    __shared__ __nv_bfloat16 AsH[128][40];   // padded: 80B row stride
    __shared__ __nv_bfloat16 AsL[128][40];
    __shared__ __nv_bfloat16 BsH[32][128];   // XOR-swizzled 16B chunks
    __shared__ __nv_bfloat16 BsL[32][128];

    int tid  = threadIdx.x;
    int lane = tid & 31, warp = tid >> 5;
    int wm0 = (warp >> 2) * 64;      // warp m base within block
    int wn0 = (warp & 3) * 32;       // warp n base within block
    int row0 = blockIdx.x * 128;
    int n0   = blockIdx.y * 128;

    float acc[4][4][4];
#pragma unroll
    for (int i = 0; i < 4; i++)
#pragma unroll
        for (int j = 0; j < 4; j++)
#pragma unroll
            for (int q = 0; q < 4; q++) acc[i][j][q] = 0.f;

    int arow = tid >> 1;             // 0..127
    int akp  = (tid & 1) * 16;       // 0 or 16
    int brow = tid >> 3;             // 0..31
    int bc   = tid & 7;              // 16-float chunk id

    uint32_t ash_base = (uint32_t)__cvta_generic_to_shared(&AsH[0][0]);
    uint32_t asl_base = (uint32_t)__cvta_generic_to_shared(&AsL[0][0]);
    uint32_t bsh_base = (uint32_t)__cvta_generic_to_shared(&BsH[0][0]);
    uint32_t bsl_base = (uint32_t)__cvta_generic_to_shared(&BsL[0][0]);

    for (int k0 = 0; k0 < KTOT; k0 += 32) {
        // ---- stage A tile (128x32 fp32 -> hi/lo bf16) ----
        {
            float av[16];
            int grow = row0 + arow;
            int k = k0 + akp;
            if (grow < NN) {
                const float* src;
                if (LAYER == 1) {
                    if (k < KA) src = g_agg1 + (size_t)grow * 128 + k;
                    else src = ((grow < NM) ? movie + (size_t)grow * 128
                                            : user + (size_t)(grow - NM) * 128) + (k - KA);
                } else {
                    src = (k < KA) ? g_agg2 + (size_t)grow * 256 + k
                                   : g_h + (size_t)grow * 256 + (k - KA);
                }
#pragma unroll
                for (int i = 0; i < 4; i++)
                    *(float4*)(av + i * 4) = *(const float4*)(src + i * 4);
            } else {
#pragma unroll
                for (int i = 0; i < 16; i++) av[i] = 0.f;
            }
            uint32_t hp[8], lp[8];
#pragma unroll
            for (int i = 0; i < 8; i++) {
                __nv_bfloat16 h0 = __float2bfloat16(av[2 * i]);
                __nv_bfloat16 h1 = __float2bfloat16(av[2 * i + 1]);
                __nv_bfloat16 l0 = __float2bfloat16(av[2 * i] - __bfloat162float(h0));
                __nv_bfloat16 l1 = __float2bfloat16(av[2 * i + 1] - __bfloat162float(h1));
                hp[i] = pk(h0, h1);
                lp[i] = pk(l0, l1);
            }
            *(uint4*)&AsH[arow][akp]     = *(uint4*)(hp);
            *(uint4*)&AsH[arow][akp + 8] = *(uint4*)(hp + 4);
            *(uint4*)&AsL[arow][akp]     = *(uint4*)(lp);
            *(uint4*)&AsL[arow][akp + 8] = *(uint4*)(lp + 4);
        }
        // ---- stage B tile (32x128 fp32 -> hi/lo bf16, XOR swizzle) ----
        {
            int kk = k0 + brow;
            const float* bsrc = (kk < KA)
                ? Wl + (size_t)kk * NOUT + n0 + bc * 16
                : Wr + (size_t)(kk - KA) * NOUT + n0 + bc * 16;
            float bv[16];
#pragma unroll
            for (int i = 0; i < 4; i++)
                *(float4*)(bv + i * 4) = *(const float4*)(bsrc + i * 4);
#pragma unroll
            for (int half = 0; half < 2; half++) {
                uint32_t hp[4], lp[4];
#pragma unroll
                for (int i = 0; i < 4; i++) {
                    float v0 = bv[half * 8 + 2 * i];
                    float v1 = bv[half * 8 + 2 * i + 1];
                    __nv_bfloat16 h0 = __float2bfloat16(v0);
                    __nv_bfloat16 h1 = __float2bfloat16(v1);
                    __nv_bfloat16 l0 = __float2bfloat16(v0 - __bfloat162float(h0));
                    __nv_bfloat16 l1 = __float2bfloat16(v1 - __bfloat162float(h1));
                    hp[i] = pk(h0, h1);
                    lp[i] = pk(l0, l1);
                }
                int c = bc * 2 + half;            // 16-byte chunk 0..15
                int sw = (c ^ (brow & 7)) << 4;   // byte offset within row
                *(uint4*)((char*)BsH + (size_t)brow * 256 + (size_t)sw) = *(uint4*)(hp);
                *(uint4*)((char*)BsL + (size_t)brow * 256 + (size_t)sw) = *(uint4*)(lp);
            }
        }
        __syncthreads();

        // ---- two k16 steps of mma ----
#pragma unroll
        for (int ks = 0; ks < 2; ks++) {
            uint32_t aH[4][4], aL[4][4], bH[4][2], bL[4][2];
#pragma unroll
            for (int mt = 0; mt < 4; mt++) {
                int r  = wm0 + mt * 16 + (lane & 15);
                int kc = ks * 16 + ((lane >> 4) << 3);
                uint32_t off = (uint32_t)(r * 80 + kc * 2);
                ldsm4(aH[mt], ash_base + off);
                ldsm4(aL[mt], asl_base + off);
            }
#pragma unroll
            for (int nt = 0; nt < 4; nt++) {
                int kk = ks * 16 + (lane & 15);
                int c  = (wn0 + nt * 8) >> 3;
                uint32_t off = (uint32_t)(kk * 256 + ((c ^ (kk & 7)) << 4));
                ldsm2t(bH[nt], bsh_base + off);
                ldsm2t(bL[nt], bsl_base + off);
            }
#pragma unroll
            for (int mt = 0; mt < 4; mt++)
#pragma unroll
                for (int nt = 0; nt < 4; nt++) {
                    mma_bf16(acc[mt][nt], aH[mt], bH[nt]);
                    mma_bf16(acc[mt][nt], aH[mt], bL[nt]);
                    mma_bf16(acc[mt][nt], aL[mt], bH[nt]);
                }
        }
        __syncthreads();
    }

    // ---- epilogue: bias (+relu), write fp32 ----
    float* dst = (LAYER == 1) ? g_h : outp;
#pragma unroll
    for (int mt = 0; mt < 4; mt++) {
        int r = row0 + wm0 + mt * 16 + (lane >> 2);
#pragma unroll
        for (int nt = 0; nt < 4; nt++) {
            int colg = n0 + wn0 + nt * 8 + (lane & 3) * 2;
            float b0 = bias[colg], b1 = bias[colg + 1];
            if (r < NN) {
                float2 v;
                v.x = acc[mt][nt][0] + b0;
                v.y = acc[mt][nt][1] + b1;
                if (LAYER == 1) { v.x = fmaxf(v.x, 0.f); v.y = fmaxf(v.y, 0.f); }
                *(float2*)(dst + (size_t)r * NOUT + colg) = v;
            }
            if (r + 8 < NN) {
                float2 v;
                v.x = acc[mt][nt][2] + b0;
                v.y = acc[mt][nt][3] + b1;
                if (LAYER == 1) { v.x = fmaxf(v.x, 0.f); v.y = fmaxf(v.y, 0.f); }
                *(float2*)(dst + (size_t)(r + 8) * NOUT + colg) = v;
            }
        }
    }
}

// ---------------- edge scoring: out[e] = refined[src] . refined[dst] --------
__global__ void k_score(const void* ei, const float* __restrict__ refined,
                        float* __restrict__ out)
{
    int warp = threadIdx.x >> 5;
    int lane = threadIdx.x & 31;
    int e = blockIdx.x * 8 + warp;
    if (e >= NE) return;
    int s = edge_idx(ei, 0, e);
    int d = edge_idx(ei, 1, e);
    float4 va = ((const float4*)(refined + (size_t)s * D1))[lane];
    float4 vb = ((const float4*)(refined + (size_t)d * D1))[lane];
    float t = va.x * vb.x + va.y * vb.y + va.z * vb.z + va.w * vb.w;
#pragma unroll
    for (int o = 16; o > 0; o >>= 1) t += __shfl_xor_sync(0xFFFFFFFFu, t, o);
    if (lane == 0) out[e] = t;
}

// ---------------- launch -----------------------------------------------------
extern "C" void kernel_launch(void* const* d_in, const int* in_sizes, int n_in,
                              void* d_out, int out_size)
{
    const void*  ei    = d_in[0];
    // d_in[1] = edge_attr (unused by reference)
    const float* movie = (const float*)d_in[2];
    const float* user  = (const float*)d_in[3];
    const float* Wl1   = (const float*)d_in[4];
    const float* bl1   = (const float*)d_in[5];
    const float* Wr1   = (const float*)d_in[6];
    const float* Wl2   = (const float*)d_in[7];
    const float* bl2   = (const float*)d_in[8];
    const float* Wr2   = (const float*)d_in[9];

    float* out     = (float*)d_out;       // [NE] predicted ratings
    float* refined = out + NE;            // [NN * D1]

    const int MB = (NN + 127) / 128;      // 1172 row blocks

    k_detect<<<1, 256>>>(ei);
    k_zero<<<(NN + 255) / 256, 256>>>();
    k_count<<<(NE + 255) / 256, 256>>>(ei);
    k_scan1<<<(NN + 1023) / 1024, 1024>>>();
    k_scan2<<<1, 256>>>();
    k_scan3<<<(NN + 255) / 256, 256>>>();
    k_bucket<<<(NE + 255) / 256, 256>>>(ei);
    k_agg1<<<NN / 8, 256>>>(movie, user);
    k_gemm_tc<1><<<dim3(MB, 2), 256>>>(movie, user, Wl1, Wr1, bl1, nullptr);
    k_agg2<<<NN / 8, 256>>>();
    k_gemm_tc<2><<<dim3(MB, 1), 256>>>(movie, user, Wl2, Wr2, bl2, refined);
    k_score<<<(NE + 7) / 8, 256>>>(ei, refined, out);
}

// round 6
// speedup vs baseline: 1.9479x; 1.3753x over previous
#include <cuda_runtime.h>
#include <cuda_bf16.h>
#include <cstdint>
#include <cstddef>

#define NM 100000           // movies
#define NU 50000            // users
#define NN 150000           // total nodes
#define NE 500000           // edges
#define D1 128              // emb dim
#define D2 256              // hidden dim

// ---------------- scratch (device globals; no allocation allowed) ----------
__device__ int g_deg[NN];
__device__ int g_off[NN + 1];
__device__ int g_pos[NN];
__device__ int g_srcs[NE];
__device__ int g_bsum[256];
__device__ int g_is64;
// pre-split bf16 (hi,lo) pairs; all 16B-aligned for cp.async
__device__ __align__(256) __nv_bfloat16 g_xh[(size_t)NN * 128];
__device__ __align__(256) __nv_bfloat16 g_xl[(size_t)NN * 128];
__device__ __align__(256) __nv_bfloat16 g_a1h[(size_t)NN * 128];
__device__ __align__(256) __nv_bfloat16 g_a1l[(size_t)NN * 128];
__device__ __align__(256) __nv_bfloat16 g_hh[(size_t)NN * 256];
__device__ __align__(256) __nv_bfloat16 g_hl[(size_t)NN * 256];
__device__ __align__(256) __nv_bfloat16 g_a2h[(size_t)NN * 256];
__device__ __align__(256) __nv_bfloat16 g_a2l[(size_t)NN * 256];
// weights, k-major [k][n] (same layout as inputs), bf16 split
__device__ __align__(256) __nv_bfloat16 g_B1h[256 * 256];
__device__ __align__(256) __nv_bfloat16 g_B1l[256 * 256];
__device__ __align__(256) __nv_bfloat16 g_B2h[512 * 128];
__device__ __align__(256) __nv_bfloat16 g_B2l[512 * 128];

// ---------------- helpers ----------------------------------------------------
__device__ __forceinline__ int edge_idx(const void* ei, int which, int e) {
    if (g_is64) {
        const long long* p = (const long long*)ei;
        return (int)p[(size_t)which * NE + e];
    } else {
        const int* p = (const int*)ei;
        return p[(size_t)which * NE + e];
    }
}
__device__ __forceinline__ uint32_t pk(__nv_bfloat16 a, __nv_bfloat16 b) {
    return (uint32_t)__bfloat16_as_ushort(a) |
           ((uint32_t)__bfloat16_as_ushort(b) << 16);
}
__device__ __forceinline__ void split2(float v0, float v1, uint32_t& hp, uint32_t& lp) {
    __nv_bfloat16 h0 = __float2bfloat16(v0);
    __nv_bfloat16 h1 = __float2bfloat16(v1);
    __nv_bfloat16 l0 = __float2bfloat16(v0 - __bfloat162float(h0));
    __nv_bfloat16 l1 = __float2bfloat16(v1 - __bfloat162float(h1));
    hp = pk(h0, h1);
    lp = pk(l0, l1);
}
__device__ __forceinline__ void cpa16(uint32_t dst, const void* src) {
    asm volatile("cp.async.cg.shared.global [%0], [%1], 16;" :: "r"(dst), "l"(src));
}
__device__ __forceinline__ void cpa_commit() {
    asm volatile("cp.async.commit_group;" ::: "memory");
}
template <int N>
__device__ __forceinline__ void cpa_wait() {
    asm volatile("cp.async.wait_group %0;" :: "n"(N) : "memory");
}
__device__ __forceinline__ void ldsm4(uint32_t* r, uint32_t a) {
    asm volatile("ldmatrix.sync.aligned.m8n8.x4.shared.b16 {%0,%1,%2,%3}, [%4];"
                 : "=r"(r[0]), "=r"(r[1]), "=r"(r[2]), "=r"(r[3]) : "r"(a));
}
__device__ __forceinline__ void ldsm2t(uint32_t* r, uint32_t a) {
    asm volatile("ldmatrix.sync.aligned.m8n8.x2.trans.shared.b16 {%0,%1}, [%2];"
                 : "=r"(r[0]), "=r"(r[1]) : "r"(a));
}
__device__ __forceinline__ void mma_bf16(float* c, const uint32_t* a, const uint32_t* b) {
    asm volatile(
        "mma.sync.aligned.m16n8k16.row.col.f32.bf16.bf16.f32 "
        "{%0,%1,%2,%3},{%4,%5,%6,%7},{%8,%9},{%0,%1,%2,%3};"
        : "+f"(c[0]), "+f"(c[1]), "+f"(c[2]), "+f"(c[3])
        : "r"(a[0]), "r"(a[1]), "r"(a[2]), "r"(a[3]), "r"(b[0]), "r"(b[1]));
}

// ---------------- small kernels ----------------------------------------------
__global__ void k_detect(const void* ei) {
    const long long* p = (const long long*)ei;
    int bad = 0;
    for (int i = threadIdx.x; i < 2048; i += blockDim.x) {
        long long v = p[i];
        if (v < 0 || v >= NN) bad = 1;
    }
    bad = __syncthreads_or(bad);
    if (threadIdx.x == 0) g_is64 = bad ? 0 : 1;
}

__global__ void k_zero() {
    int i = blockIdx.x * blockDim.x + threadIdx.x;
    if (i < NN) g_deg[i] = 0;
}

__global__ void k_count(const void* ei) {
    int e = blockIdx.x * blockDim.x + threadIdx.x;
    if (e < NE) atomicAdd(&g_deg[edge_idx(ei, 1, e)], 1);
}

__global__ void k_scan1() {
    __shared__ int s[1024];
    int i = blockIdx.x * 1024 + threadIdx.x;
    int v = (i < NN) ? g_deg[i] : 0;
    s[threadIdx.x] = v;
    __syncthreads();
#pragma unroll
    for (int off = 1; off < 1024; off <<= 1) {
        int t = (threadIdx.x >= off) ? s[threadIdx.x - off] : 0;
        __syncthreads();
        s[threadIdx.x] += t;
        __syncthreads();
    }
    if (i < NN) g_off[i] = s[threadIdx.x] - v;
    if (threadIdx.x == 1023) g_bsum[blockIdx.x] = s[1023];
}

__global__ void k_scan2() {
    __shared__ int s[256];
    const int NB = (NN + 1023) / 1024;
    int v = (threadIdx.x < NB) ? g_bsum[threadIdx.x] : 0;
    s[threadIdx.x] = v;
    __syncthreads();
#pragma unroll
    for (int off = 1; off < 256; off <<= 1) {
        int t = (threadIdx.x >= off) ? s[threadIdx.x - off] : 0;
        __syncthreads();
        s[threadIdx.x] += t;
        __syncthreads();
    }
    if (threadIdx.x < NB) g_bsum[threadIdx.x] = s[threadIdx.x] - v;
}

__global__ void k_scan3() {
    int i = blockIdx.x * blockDim.x + threadIdx.x;
    if (i < NN) {
        int val = g_off[i] + g_bsum[i >> 10];
        g_off[i] = val;
        g_pos[i] = val;
    }
    if (i == 0) g_off[NN] = NE;
}

__global__ void k_bucket(const void* ei) {
    int e = blockIdx.x * blockDim.x + threadIdx.x;
    if (e < NE) {
        int d = edge_idx(ei, 1, e);
        int p = atomicAdd(&g_pos[d], 1);
        g_srcs[p] = edge_idx(ei, 0, e);
    }
}

// weights -> bf16 hi/lo split, k-major (layout unchanged)
__global__ void k_split_w(const float* __restrict__ Wl1, const float* __restrict__ Wr1,
                          const float* __restrict__ Wl2, const float* __restrict__ Wr2)
{
    int i = blockIdx.x * blockDim.x + threadIdx.x;
    if (i < 65536) {                       // B1 [256][256]
        float v = (i < 32768) ? Wl1[i] : Wr1[i - 32768];
        __nv_bfloat16 h = __float2bfloat16(v);
        g_B1h[i] = h;
        g_B1l[i] = __float2bfloat16(v - __bfloat162float(h));
    } else if (i < 131072) {               // B2 [512][128]
        int j = i - 65536;
        float v = (j < 32768) ? Wl2[j] : Wr2[j - 32768];
        __nv_bfloat16 h = __float2bfloat16(v);
        g_B2h[j] = h;
        g_B2l[j] = __float2bfloat16(v - __bfloat162float(h));
    }
}

// embeddings -> bf16 hi/lo split
__global__ void k_split_x(const float* __restrict__ movie, const float* __restrict__ user) {
    int i = (blockIdx.x * blockDim.x + threadIdx.x) * 4;
    if (i >= NN * 128) return;
    int row = i >> 7, col = i & 127;
    const float* src = (row < NM) ? movie + (size_t)row * 128 + col
                                  : user + (size_t)(row - NM) * 128 + col;
    float4 v = *(const float4*)src;
    uint32_t h0, l0, h1, l1;
    split2(v.x, v.y, h0, l0);
    split2(v.z, v.w, h1, l1);
    uint2 hv = make_uint2(h0, h1), lv = make_uint2(l0, l1);
    *(uint2*)(g_xh + i) = hv;
    *(uint2*)(g_xl + i) = lv;
}

// ---------------- aggregations (split bf16 outputs) --------------------------
__global__ void k_agg1(const float* __restrict__ movie, const float* __restrict__ user) {
    int warp = threadIdx.x >> 5;
    int lane = threadIdx.x & 31;
    int node = blockIdx.x * 8 + warp;
    if (node >= NN) return;
    int beg = g_off[node], end = g_off[node + 1];
    float4 acc = make_float4(0.f, 0.f, 0.f, 0.f);
    for (int e = beg; e < end; e++) {
        int s = g_srcs[e];
        const float4* row = (s < NM)
            ? (const float4*)(movie + (size_t)s * D1)
            : (const float4*)(user + (size_t)(s - NM) * D1);
        float4 v = row[lane];
        acc.x += v.x; acc.y += v.y; acc.z += v.z; acc.w += v.w;
    }
    int cnt = end - beg;
    float inv = 1.0f / (float)(cnt > 0 ? cnt : 1);
    acc.x *= inv; acc.y *= inv; acc.z *= inv; acc.w *= inv;
    uint32_t h0, l0, h1, l1;
    split2(acc.x, acc.y, h0, l0);
    split2(acc.z, acc.w, h1, l1);
    *(uint2*)(g_a1h + (size_t)node * 128 + lane * 4) = make_uint2(h0, h1);
    *(uint2*)(g_a1l + (size_t)node * 128 + lane * 4) = make_uint2(l0, l1);
}

__global__ void k_agg2() {
    int warp = threadIdx.x >> 5;
    int lane = threadIdx.x & 31;
    int node = blockIdx.x * 8 + warp;
    if (node >= NN) return;
    int beg = g_off[node], end = g_off[node + 1];
    float a[8];
#pragma unroll
    for (int i = 0; i < 8; i++) a[i] = 0.f;
    for (int e = beg; e < end; e++) {
        int s = g_srcs[e];
        uint4 hv = ((const uint4*)(g_hh + (size_t)s * 256))[lane];
        uint4 lv = ((const uint4*)(g_hl + (size_t)s * 256))[lane];
        const uint32_t* hp = (const uint32_t*)&hv;
        const uint32_t* lp = (const uint32_t*)&lv;
#pragma unroll
        for (int i = 0; i < 4; i++) {
            float2 h2 = __bfloat1622float2(*(const __nv_bfloat162*)&hp[i]);
            float2 l2 = __bfloat1622float2(*(const __nv_bfloat162*)&lp[i]);
            a[2 * i]     += h2.x + l2.x;
            a[2 * i + 1] += h2.y + l2.y;
        }
    }
    int cnt = end - beg;
    float inv = 1.0f / (float)(cnt > 0 ? cnt : 1);
    uint32_t hp[4], lp[4];
#pragma unroll
    for (int i = 0; i < 4; i++)
        split2(a[2 * i] * inv, a[2 * i + 1] * inv, hp[i], lp[i]);
    *(uint4*)(g_a2h + (size_t)node * 256 + lane * 8) = *(uint4*)hp;
    *(uint4*)(g_a2l + (size_t)node * 256 + lane * 8) = *(uint4*)lp;
}

// ---------------- pipelined HMMA GEMM ----------------------------------------
// LAYER 1: A=[a1|x] [NN,256]  B1[256,256] -> h(split) = relu(A@B1 + b1)
// LAYER 2: A=[a2|h] [NN,512]  B2[512,128] -> refined fp32 = A@B2 + b2
// BM=128 BN=128 BK=32, 256 thr, warp tile 64x32, 3-term split (HH+HL+LH).
// 2-stage cp.async pipeline; per-stage smem: AH10240|AL10240|BH8192|BL8192.
template <int LAYER>
__global__ void __launch_bounds__(256, 2) k_gemm_cp(
    const float* __restrict__ bias, float* __restrict__ outp)
{
    constexpr int KTOT = (LAYER == 1) ? 256 : 512;
    constexpr int NOUT = (LAYER == 1) ? 256 : 128;
    constexpr int KA   = (LAYER == 1) ? 128 : 256;
    constexpr int NCH  = KTOT / 32;
    constexpr int STG  = 36864;

    extern __shared__ char smr[];
    uint32_t sm0 = (uint32_t)__cvta_generic_to_shared(smr);

    int tid = threadIdx.x, lane = tid & 31, warp = tid >> 5;
    int wm0 = (warp >> 2) * 64, wn0 = (warp & 3) * 32;
    int row0 = blockIdx.x * 128, n0 = blockIdx.y * 128;

    float acc[4][4][4];
#pragma unroll
    for (int i = 0; i < 4; i++)
#pragma unroll
        for (int j = 0; j < 4; j++)
#pragma unroll
            for (int q = 0; q < 4; q++) acc[i][j][q] = 0.f;

    auto stage = [&](int ch, int s) {
        uint32_t sb = sm0 + (uint32_t)(s * STG);
        // A: 128 rows x 32 k; 16B = 8 k; 512 chunks per buf
#pragma unroll
        for (int i = 0; i < 2; i++) {
            int idx = tid + i * 256;
            int row = idx >> 2, c = idx & 3;
            int grow = row0 + row;
            if (grow >= NN) grow = 0;
            int kk = ch * 32 + c * 8;
            const __nv_bfloat16 *sh, *sl;
            if (LAYER == 1) {
                if (kk < KA) { sh = g_a1h + (size_t)grow * 128 + kk;
                               sl = g_a1l + (size_t)grow * 128 + kk; }
                else         { sh = g_xh  + (size_t)grow * 128 + (kk - KA);
                               sl = g_xl  + (size_t)grow * 128 + (kk - KA); }
            } else {
                if (kk < KA) { sh = g_a2h + (size_t)grow * 256 + kk;
                               sl = g_a2l + (size_t)grow * 256 + kk; }
                else         { sh = g_hh  + (size_t)grow * 256 + (kk - KA);
                               sl = g_hl  + (size_t)grow * 256 + (kk - KA); }
            }
            uint32_t d = sb + (uint32_t)(row * 80 + c * 16);
            cpa16(d, sh);
            cpa16(d + 10240, sl);
        }
        // B: 32 k rows x 128 n; 16B = 8 n; XOR swizzle as validated
#pragma unroll
        for (int i = 0; i < 2; i++) {
            int idx = tid + i * 256;
            int k = idx >> 4, c = idx & 15;
            int kg = ch * 32 + k;
            const __nv_bfloat16 *sh, *sl;
            if (LAYER == 1) { sh = g_B1h + (size_t)kg * 256 + n0 + c * 8;
                              sl = g_B1l + (size_t)kg * 256 + n0 + c * 8; }
            else            { sh = g_B2h + (size_t)kg * 128 + c * 8;
                              sl = g_B2l + (size_t)kg * 128 + c * 8; }
            uint32_t d = sb + 20480u + (uint32_t)(k * 256 + ((c ^ (k & 7)) << 4));
            cpa16(d, sh);
            cpa16(d + 8192, sl);
        }
    };

    stage(0, 0);
    cpa_commit();

    for (int ch = 0; ch < NCH; ch++) {
        int s = ch & 1;
        if (ch + 1 < NCH) {
            stage(ch + 1, (ch + 1) & 1);
            cpa_commit();
            cpa_wait<1>();
        } else {
            cpa_wait<0>();
        }
        __syncthreads();

        uint32_t ah = sm0 + (uint32_t)(s * STG);
        uint32_t al = ah + 10240;
        uint32_t bh = ah + 20480;
        uint32_t bl = ah + 28672;
#pragma unroll
        for (int ks = 0; ks < 2; ks++) {
            uint32_t aH[4][4], aL[4][4];
#pragma unroll
            for (int mt = 0; mt < 4; mt++) {
                int r  = wm0 + mt * 16 + (lane & 15);
                int kc = ks * 16 + ((lane >> 4) << 3);
                uint32_t off = (uint32_t)(r * 80 + kc * 2);
                ldsm4(aH[mt], ah + off);
                ldsm4(aL[mt], al + off);
            }
#pragma unroll
            for (int nt = 0; nt < 4; nt++) {
                int kk = ks * 16 + (lane & 15);
                int cc = (wn0 + nt * 8) >> 3;
                uint32_t off = (uint32_t)(kk * 256 + ((cc ^ (kk & 7)) << 4));
                uint32_t bH[2], bL[2];
                ldsm2t(bH, bh + off);
                ldsm2t(bL, bl + off);
#pragma unroll
                for (int mt = 0; mt < 4; mt++) {
                    mma_bf16(acc[mt][nt], aH[mt], bH);
                    mma_bf16(acc[mt][nt], aH[mt], bL);
                    mma_bf16(acc[mt][nt], aL[mt], bH);
                }
            }
        }
        __syncthreads();
    }

    // ---- epilogue ----
#pragma unroll
    for (int mt = 0; mt < 4; mt++) {
        int r = row0 + wm0 + mt * 16 + (lane >> 2);
#pragma unroll
        for (int nt = 0; nt < 4; nt++) {
            int colg = n0 + wn0 + nt * 8 + (lane & 3) * 2;
            float b0 = bias[colg], b1 = bias[colg + 1];
#pragma unroll
            for (int half = 0; half < 2; half++) {
                int rr = r + half * 8;
                if (rr >= NN) continue;
                float vx = acc[mt][nt][half * 2]     + b0;
                float vy = acc[mt][nt][half * 2 + 1] + b1;
                if (LAYER == 1) {
                    vx = fmaxf(vx, 0.f);
                    vy = fmaxf(vy, 0.f);
                    uint32_t hp, lp;
                    split2(vx, vy, hp, lp);
                    *(uint32_t*)(g_hh + (size_t)rr * 256 + colg) = hp;
                    *(uint32_t*)(g_hl + (size_t)rr * 256 + colg) = lp;
                } else {
                    float2 v = make_float2(vx, vy);
                    *(float2*)(outp + (size_t)rr * NOUT + colg) = v;
                }
            }
        }
    }
}

// ---------------- edge scoring ----------------------------------------------
__global__ void k_score(const void* ei, const float* __restrict__ refined,
                        float* __restrict__ out)
{
    int warp = threadIdx.x >> 5;
    int lane = threadIdx.x & 31;
    int e = blockIdx.x * 8 + warp;
    if (e >= NE) return;
    int s = edge_idx(ei, 0, e);
    int d = edge_idx(ei, 1, e);
    float4 va = ((const float4*)(refined + (size_t)s * D1))[lane];
    float4 vb = ((const float4*)(refined + (size_t)d * D1))[lane];
    float t = va.x * vb.x + va.y * vb.y + va.z * vb.z + va.w * vb.w;
#pragma unroll
    for (int o = 16; o > 0; o >>= 1) t += __shfl_xor_sync(0xFFFFFFFFu, t, o);
    if (lane == 0) out[e] = t;
}

// ---------------- launch -----------------------------------------------------
extern "C" void kernel_launch(void* const* d_in, const int* in_sizes, int n_in,
                              void* d_out, int out_size)
{
    const void*  ei    = d_in[0];
    const float* movie = (const float*)d_in[2];
    const float* user  = (const float*)d_in[3];
    const float* Wl1   = (const float*)d_in[4];
    const float* bl1   = (const float*)d_in[5];
    const float* Wr1   = (const float*)d_in[6];
    const float* Wl2   = (const float*)d_in[7];
    const float* bl2   = (const float*)d_in[8];
    const float* Wr2   = (const float*)d_in[9];

    float* out     = (float*)d_out;
    float* refined = out + NE;

    const int MB = (NN + 127) / 128;      // 1172
    const int SMEM = 2 * 36864;           // 73728

    static int attr_done = 0;
    cudaFuncSetAttribute(k_gemm_cp<1>, cudaFuncAttributeMaxDynamicSharedMemorySize, SMEM);
    cudaFuncSetAttribute(k_gemm_cp<2>, cudaFuncAttributeMaxDynamicSharedMemorySize, SMEM);
    (void)attr_done;

    k_detect<<<1, 256>>>(ei);
    k_split_w<<<512, 256>>>(Wl1, Wr1, Wl2, Wr2);
    k_split_x<<<(NN * 128 / 4 + 255) / 256, 256>>>(movie, user);
    k_zero<<<(NN + 255) / 256, 256>>>();
    k_count<<<(NE + 255) / 256, 256>>>(ei);
    k_scan1<<<(NN + 1023) / 1024, 1024>>>();
    k_scan2<<<1, 256>>>();
    k_scan3<<<(NN + 255) / 256, 256>>>();
    k_bucket<<<(NE + 255) / 256, 256>>>(ei);
    k_agg1<<<NN / 8, 256>>>(movie, user);
    k_gemm_cp<1><<<dim3(MB, 2), 256, SMEM>>>(bl1, nullptr);
    k_agg2<<<NN / 8, 256>>>();
    k_gemm_cp<2><<<dim3(MB, 1), 256, SMEM>>>(bl2, refined);
    k_score<<<(NE + 7) / 8, 256>>>(ei, refined, out);
}

// round 7
// speedup vs baseline: 2.2321x; 1.1459x over previous
#include <cuda_runtime.h>
#include <cuda_bf16.h>
#include <cuda_fp16.h>
#include <cstdint>
#include <cstddef>

#define NM 100000           // movies
#define NU 50000            // users
#define NN 150000           // total nodes
#define NE 500000           // edges
#define D1 128              // emb dim
#define D2 256              // hidden dim

// ---------------- scratch (device globals; no allocation allowed) ----------
__device__ int g_deg[NN];
__device__ int g_off[NN + 1];
__device__ int g_pos[NN];
__device__ int g_srcs[NE];
__device__ int g_bsum[256];
__device__ int g_is64;
// layer-1 operands: single fp16
__device__ __align__(256) __half g_xf[(size_t)NN * 128];
__device__ __align__(256) __half g_a1f[(size_t)NN * 128];
__device__ __align__(256) __half g_B1f[256 * 256];
// layer-2 operands: bf16 hi/lo split (fp32-accurate path)
__device__ __align__(256) __nv_bfloat16 g_hh[(size_t)NN * 256];
__device__ __align__(256) __nv_bfloat16 g_hl[(size_t)NN * 256];
__device__ __align__(256) __nv_bfloat16 g_a2h[(size_t)NN * 256];
__device__ __align__(256) __nv_bfloat16 g_a2l[(size_t)NN * 256];
__device__ __align__(256) __nv_bfloat16 g_B2h[512 * 128];
__device__ __align__(256) __nv_bfloat16 g_B2l[512 * 128];

// ---------------- helpers ----------------------------------------------------
__device__ __forceinline__ int edge_idx(const void* ei, int which, int e) {
    if (g_is64) {
        const long long* p = (const long long*)ei;
        return (int)p[(size_t)which * NE + e];
    } else {
        const int* p = (const int*)ei;
        return p[(size_t)which * NE + e];
    }
}
__device__ __forceinline__ uint32_t pk(__nv_bfloat16 a, __nv_bfloat16 b) {
    return (uint32_t)__bfloat16_as_ushort(a) |
           ((uint32_t)__bfloat16_as_ushort(b) << 16);
}
__device__ __forceinline__ void split2(float v0, float v1, uint32_t& hp, uint32_t& lp) {
    __nv_bfloat16 h0 = __float2bfloat16(v0);
    __nv_bfloat16 h1 = __float2bfloat16(v1);
    __nv_bfloat16 l0 = __float2bfloat16(v0 - __bfloat162float(h0));
    __nv_bfloat16 l1 = __float2bfloat16(v1 - __bfloat162float(h1));
    hp = pk(h0, h1);
    lp = pk(l0, l1);
}
__device__ __forceinline__ uint32_t pkh(float a, float b) {
    __half2 p = __floats2half2_rn(a, b);
    return *(uint32_t*)&p;
}
__device__ __forceinline__ void cpa16(uint32_t dst, const void* src) {
    asm volatile("cp.async.cg.shared.global [%0], [%1], 16;" :: "r"(dst), "l"(src));
}
__device__ __forceinline__ void cpa_commit() {
    asm volatile("cp.async.commit_group;" ::: "memory");
}
template <int N>
__device__ __forceinline__ void cpa_wait() {
    asm volatile("cp.async.wait_group %0;" :: "n"(N) : "memory");
}
__device__ __forceinline__ void ldsm4(uint32_t* r, uint32_t a) {
    asm volatile("ldmatrix.sync.aligned.m8n8.x4.shared.b16 {%0,%1,%2,%3}, [%4];"
                 : "=r"(r[0]), "=r"(r[1]), "=r"(r[2]), "=r"(r[3]) : "r"(a));
}
__device__ __forceinline__ void ldsm2t(uint32_t* r, uint32_t a) {
    asm volatile("ldmatrix.sync.aligned.m8n8.x2.trans.shared.b16 {%0,%1}, [%2];"
                 : "=r"(r[0]), "=r"(r[1]) : "r"(a));
}
__device__ __forceinline__ void mma_bf16(float* c, const uint32_t* a, const uint32_t* b) {
    asm volatile(
        "mma.sync.aligned.m16n8k16.row.col.f32.bf16.bf16.f32 "
        "{%0,%1,%2,%3},{%4,%5,%6,%7},{%8,%9},{%0,%1,%2,%3};"
        : "+f"(c[0]), "+f"(c[1]), "+f"(c[2]), "+f"(c[3])
        : "r"(a[0]), "r"(a[1]), "r"(a[2]), "r"(a[3]), "r"(b[0]), "r"(b[1]));
}
__device__ __forceinline__ void mma_f16(float* c, const uint32_t* a, const uint32_t* b) {
    asm volatile(
        "mma.sync.aligned.m16n8k16.row.col.f32.f16.f16.f32 "
        "{%0,%1,%2,%3},{%4,%5,%6,%7},{%8,%9},{%0,%1,%2,%3};"
        : "+f"(c[0]), "+f"(c[1]), "+f"(c[2]), "+f"(c[3])
        : "r"(a[0]), "r"(a[1]), "r"(a[2]), "r"(a[3]), "r"(b[0]), "r"(b[1]));
}

// ---------------- small kernels ----------------------------------------------
__global__ void k_detect(const void* ei) {
    const long long* p = (const long long*)ei;
    int bad = 0;
    for (int i = threadIdx.x; i < 2048; i += blockDim.x) {
        long long v = p[i];
        if (v < 0 || v >= NN) bad = 1;
    }
    bad = __syncthreads_or(bad);
    if (threadIdx.x == 0) g_is64 = bad ? 0 : 1;
}

__global__ void k_zero() {
    int i = blockIdx.x * blockDim.x + threadIdx.x;
    if (i < NN) g_deg[i] = 0;
}

__global__ void k_count(const void* ei) {
    int e = blockIdx.x * blockDim.x + threadIdx.x;
    if (e < NE) atomicAdd(&g_deg[edge_idx(ei, 1, e)], 1);
}

__global__ void k_scan1() {
    __shared__ int s[1024];
    int i = blockIdx.x * 1024 + threadIdx.x;
    int v = (i < NN) ? g_deg[i] : 0;
    s[threadIdx.x] = v;
    __syncthreads();
#pragma unroll
    for (int off = 1; off < 1024; off <<= 1) {
        int t = (threadIdx.x >= off) ? s[threadIdx.x - off] : 0;
        __syncthreads();
        s[threadIdx.x] += t;
        __syncthreads();
    }
    if (i < NN) g_off[i] = s[threadIdx.x] - v;
    if (threadIdx.x == 1023) g_bsum[blockIdx.x] = s[1023];
}

__global__ void k_scan2() {
    __shared__ int s[256];
    const int NB = (NN + 1023) / 1024;
    int v = (threadIdx.x < NB) ? g_bsum[threadIdx.x] : 0;
    s[threadIdx.x] = v;
    __syncthreads();
#pragma unroll
    for (int off = 1; off < 256; off <<= 1) {
        int t = (threadIdx.x >= off) ? s[threadIdx.x - off] : 0;
        __syncthreads();
        s[threadIdx.x] += t;
        __syncthreads();
    }
    if (threadIdx.x < NB) g_bsum[threadIdx.x] = s[threadIdx.x] - v;
}

__global__ void k_scan3() {
    int i = blockIdx.x * blockDim.x + threadIdx.x;
    if (i < NN) {
        int val = g_off[i] + g_bsum[i >> 10];
        g_off[i] = val;
        g_pos[i] = val;
    }
    if (i == 0) g_off[NN] = NE;
}

__global__ void k_bucket(const void* ei) {
    int e = blockIdx.x * blockDim.x + threadIdx.x;
    if (e < NE) {
        int d = edge_idx(ei, 1, e);
        int p = atomicAdd(&g_pos[d], 1);
        g_srcs[p] = edge_idx(ei, 0, e);
    }
}

// weights: B1 -> single fp16; B2 -> bf16 hi/lo split (k-major layout kept)
__global__ void k_split_w(const float* __restrict__ Wl1, const float* __restrict__ Wr1,
                          const float* __restrict__ Wl2, const float* __restrict__ Wr2)
{
    int i = blockIdx.x * blockDim.x + threadIdx.x;
    if (i < 65536) {                       // B1 [256][256]
        float v = (i < 32768) ? Wl1[i] : Wr1[i - 32768];
        g_B1f[i] = __float2half(v);
    } else if (i < 131072) {               // B2 [512][128]
        int j = i - 65536;
        float v = (j < 32768) ? Wl2[j] : Wr2[j - 32768];
        __nv_bfloat16 h = __float2bfloat16(v);
        g_B2h[j] = h;
        g_B2l[j] = __float2bfloat16(v - __bfloat162float(h));
    }
}

// embeddings -> single fp16
__global__ void k_split_x(const float* __restrict__ movie, const float* __restrict__ user) {
    int i = (blockIdx.x * blockDim.x + threadIdx.x) * 4;
    if (i >= NN * 128) return;
    int row = i >> 7, col = i & 127;
    const float* src = (row < NM) ? movie + (size_t)row * 128 + col
                                  : user + (size_t)(row - NM) * 128 + col;
    float4 v = *(const float4*)src;
    uint2 u = make_uint2(pkh(v.x, v.y), pkh(v.z, v.w));
    *(uint2*)(g_xf + i) = u;
}

// ---------------- aggregations -----------------------------------------------
__global__ void k_agg1(const float* __restrict__ movie, const float* __restrict__ user) {
    int warp = threadIdx.x >> 5;
    int lane = threadIdx.x & 31;
    int node = blockIdx.x * 8 + warp;
    if (node >= NN) return;
    int beg = g_off[node], end = g_off[node + 1];
    float4 acc = make_float4(0.f, 0.f, 0.f, 0.f);
    for (int e = beg; e < end; e++) {
        int s = g_srcs[e];
        const float4* row = (s < NM)
            ? (const float4*)(movie + (size_t)s * D1)
            : (const float4*)(user + (size_t)(s - NM) * D1);
        float4 v = row[lane];
        acc.x += v.x; acc.y += v.y; acc.z += v.z; acc.w += v.w;
    }
    int cnt = end - beg;
    float inv = 1.0f / (float)(cnt > 0 ? cnt : 1);
    acc.x *= inv; acc.y *= inv; acc.z *= inv; acc.w *= inv;
    uint2 u = make_uint2(pkh(acc.x, acc.y), pkh(acc.z, acc.w));
    *(uint2*)(g_a1f + (size_t)node * 128 + lane * 4) = u;
}

__global__ void k_agg2() {
    int warp = threadIdx.x >> 5;
    int lane = threadIdx.x & 31;
    int node = blockIdx.x * 8 + warp;
    if (node >= NN) return;
    int beg = g_off[node], end = g_off[node + 1];
    float a[8];
#pragma unroll
    for (int i = 0; i < 8; i++) a[i] = 0.f;
    for (int e = beg; e < end; e++) {
        int s = g_srcs[e];
        uint4 hv = ((const uint4*)(g_hh + (size_t)s * 256))[lane];
        uint4 lv = ((const uint4*)(g_hl + (size_t)s * 256))[lane];
        const uint32_t* hp = (const uint32_t*)&hv;
        const uint32_t* lp = (const uint32_t*)&lv;
#pragma unroll
        for (int i = 0; i < 4; i++) {
            float2 h2 = __bfloat1622float2(*(const __nv_bfloat162*)&hp[i]);
            float2 l2 = __bfloat1622float2(*(const __nv_bfloat162*)&lp[i]);
            a[2 * i]     += h2.x + l2.x;
            a[2 * i + 1] += h2.y + l2.y;
        }
    }
    int cnt = end - beg;
    float inv = 1.0f / (float)(cnt > 0 ? cnt : 1);
    uint32_t hp[4], lp[4];
#pragma unroll
    for (int i = 0; i < 4; i++)
        split2(a[2 * i] * inv, a[2 * i + 1] * inv, hp[i], lp[i]);
    *(uint4*)(g_a2h + (size_t)node * 256 + lane * 8) = *(uint4*)hp;
    *(uint4*)(g_a2l + (size_t)node * 256 + lane * 8) = *(uint4*)lp;
}

// ---------------- GEMM1: single fp16, pipelined ------------------------------
// A=[a1|x] [NN,256] fp16, B1 [256,256] fp16 -> h(split bf16) = relu(A@B1+b1)
// BM=128 BN=128 BK=32, grid (MB,2). Stage: A 10240B | B 8192B; 2 stages.
__global__ void __launch_bounds__(256, 2) k_gemm1_f16(
    const float* __restrict__ bias)
{
    constexpr int NCH = 8;              // 256 / 32
    constexpr int STG = 18432;

    extern __shared__ char smr[];
    uint32_t sm0 = (uint32_t)__cvta_generic_to_shared(smr);

    int tid = threadIdx.x, lane = tid & 31, warp = tid >> 5;
    int wm0 = (warp >> 2) * 64, wn0 = (warp & 3) * 32;
    int row0 = blockIdx.x * 128, n0 = blockIdx.y * 128;

    float acc[4][4][4];
#pragma unroll
    for (int i = 0; i < 4; i++)
#pragma unroll
        for (int j = 0; j < 4; j++)
#pragma unroll
            for (int q = 0; q < 4; q++) acc[i][j][q] = 0.f;

    auto stage = [&](int ch, int s) {
        uint32_t sb = sm0 + (uint32_t)(s * STG);
        // A: 128 rows x 32 k fp16; 4 x 16B chunks per row, 512 total
#pragma unroll
        for (int i = 0; i < 2; i++) {
            int idx = tid + i * 256;
            int row = idx >> 2, c = idx & 3;
            int grow = row0 + row;
            if (grow >= NN) grow = 0;
            int kk = ch * 32 + c * 8;
            const __half* src = (kk < 128)
                ? g_a1f + (size_t)grow * 128 + kk
                : g_xf  + (size_t)grow * 128 + (kk - 128);
            cpa16(sb + (uint32_t)(row * 80 + c * 16), src);
        }
        // B: 32 k x 128 n fp16; XOR-swizzled 16B chunks, 512 total
#pragma unroll
        for (int i = 0; i < 2; i++) {
            int idx = tid + i * 256;
            int k = idx >> 4, c = idx & 15;
            int kg = ch * 32 + k;
            const __half* src = g_B1f + (size_t)kg * 256 + n0 + c * 8;
            cpa16(sb + 10240u + (uint32_t)(k * 256 + ((c ^ (k & 7)) << 4)), src);
        }
    };

    stage(0, 0);
    cpa_commit();

    for (int ch = 0; ch < NCH; ch++) {
        int s = ch & 1;
        if (ch + 1 < NCH) {
            stage(ch + 1, (ch + 1) & 1);
            cpa_commit();
            cpa_wait<1>();
        } else {
            cpa_wait<0>();
        }
        __syncthreads();

        uint32_t ab = sm0 + (uint32_t)(s * STG);
        uint32_t bb = ab + 10240;
#pragma unroll
        for (int ks = 0; ks < 2; ks++) {
            uint32_t aF[4][4];
#pragma unroll
            for (int mt = 0; mt < 4; mt++) {
                int r  = wm0 + mt * 16 + (lane & 15);
                int kc = ks * 16 + ((lane >> 4) << 3);
                ldsm4(aF[mt], ab + (uint32_t)(r * 80 + kc * 2));
            }
#pragma unroll
            for (int nt = 0; nt < 4; nt++) {
                int kk = ks * 16 + (lane & 15);
                int cc = (wn0 + nt * 8) >> 3;
                uint32_t bF[2];
                ldsm2t(bF, bb + (uint32_t)(kk * 256 + ((cc ^ (kk & 7)) << 4)));
#pragma unroll
                for (int mt = 0; mt < 4; mt++)
                    mma_f16(acc[mt][nt], aF[mt], bF);
            }
        }
        __syncthreads();
    }

    // epilogue: bias + relu, write split bf16 h
#pragma unroll
    for (int mt = 0; mt < 4; mt++) {
        int r = row0 + wm0 + mt * 16 + (lane >> 2);
#pragma unroll
        for (int nt = 0; nt < 4; nt++) {
            int colg = n0 + wn0 + nt * 8 + (lane & 3) * 2;
            float b0 = bias[colg], b1 = bias[colg + 1];
#pragma unroll
            for (int half = 0; half < 2; half++) {
                int rr = r + half * 8;
                if (rr >= NN) continue;
                float vx = fmaxf(acc[mt][nt][half * 2]     + b0, 0.f);
                float vy = fmaxf(acc[mt][nt][half * 2 + 1] + b1, 0.f);
                uint32_t hp, lp;
                split2(vx, vy, hp, lp);
                *(uint32_t*)(g_hh + (size_t)rr * 256 + colg) = hp;
                *(uint32_t*)(g_hl + (size_t)rr * 256 + colg) = lp;
            }
        }
    }
}

// ---------------- GEMM2: 3-term bf16 split, pipelined (round-6 verified) -----
__global__ void __launch_bounds__(256, 2) k_gemm2_cp(
    const float* __restrict__ bias, float* __restrict__ outp)
{
    constexpr int KTOT = 512, NOUT = 128, KA = 256;
    constexpr int NCH = KTOT / 32;
    constexpr int STG = 36864;

    extern __shared__ char smr[];
    uint32_t sm0 = (uint32_t)__cvta_generic_to_shared(smr);

    int tid = threadIdx.x, lane = tid & 31, warp = tid >> 5;
    int wm0 = (warp >> 2) * 64, wn0 = (warp & 3) * 32;
    int row0 = blockIdx.x * 128;

    float acc[4][4][4];
#pragma unroll
    for (int i = 0; i < 4; i++)
#pragma unroll
        for (int j = 0; j < 4; j++)
#pragma unroll
            for (int q = 0; q < 4; q++) acc[i][j][q] = 0.f;

    auto stage = [&](int ch, int s) {
        uint32_t sb = sm0 + (uint32_t)(s * STG);
#pragma unroll
        for (int i = 0; i < 2; i++) {
            int idx = tid + i * 256;
            int row = idx >> 2, c = idx & 3;
            int grow = row0 + row;
            if (grow >= NN) grow = 0;
            int kk = ch * 32 + c * 8;
            const __nv_bfloat16 *sh, *sl;
            if (kk < KA) { sh = g_a2h + (size_t)grow * 256 + kk;
                           sl = g_a2l + (size_t)grow * 256 + kk; }
            else         { sh = g_hh  + (size_t)grow * 256 + (kk - KA);
                           sl = g_hl  + (size_t)grow * 256 + (kk - KA); }
            uint32_t d = sb + (uint32_t)(row * 80 + c * 16);
            cpa16(d, sh);
            cpa16(d + 10240, sl);
        }
#pragma unroll
        for (int i = 0; i < 2; i++) {
            int idx = tid + i * 256;
            int k = idx >> 4, c = idx & 15;
            int kg = ch * 32 + k;
            const __nv_bfloat16* sh = g_B2h + (size_t)kg * 128 + c * 8;
            const __nv_bfloat16* sl = g_B2l + (size_t)kg * 128 + c * 8;
            uint32_t d = sb + 20480u + (uint32_t)(k * 256 + ((c ^ (k & 7)) << 4));
            cpa16(d, sh);
            cpa16(d + 8192, sl);
        }
    };

    stage(0, 0);
    cpa_commit();

    for (int ch = 0; ch < NCH; ch++) {
        int s = ch & 1;
        if (ch + 1 < NCH) {
            stage(ch + 1, (ch + 1) & 1);
            cpa_commit();
            cpa_wait<1>();
        } else {
            cpa_wait<0>();
        }
        __syncthreads();

        uint32_t ah = sm0 + (uint32_t)(s * STG);
        uint32_t al = ah + 10240;
        uint32_t bh = ah + 20480;
        uint32_t bl = ah + 28672;
#pragma unroll
        for (int ks = 0; ks < 2; ks++) {
            uint32_t aH[4][4], aL[4][4];
#pragma unroll
            for (int mt = 0; mt < 4; mt++) {
                int r  = wm0 + mt * 16 + (lane & 15);
                int kc = ks * 16 + ((lane >> 4) << 3);
                uint32_t off = (uint32_t)(r * 80 + kc * 2);
                ldsm4(aH[mt], ah + off);
                ldsm4(aL[mt], al + off);
            }
#pragma unroll
            for (int nt = 0; nt < 4; nt++) {
                int kk = ks * 16 + (lane & 15);
                int cc = (wn0 + nt * 8) >> 3;
                uint32_t off = (uint32_t)(kk * 256 + ((cc ^ (kk & 7)) << 4));
                uint32_t bH[2], bL[2];
                ldsm2t(bH, bh + off);
                ldsm2t(bL, bl + off);
#pragma unroll
                for (int mt = 0; mt < 4; mt++) {
                    mma_bf16(acc[mt][nt], aH[mt], bH);
                    mma_bf16(acc[mt][nt], aH[mt], bL);
                    mma_bf16(acc[mt][nt], aL[mt], bH);
                }
            }
        }
        __syncthreads();
    }

#pragma unroll
    for (int mt = 0; mt < 4; mt++) {
        int r = row0 + wm0 + mt * 16 + (lane >> 2);
#pragma unroll
        for (int nt = 0; nt < 4; nt++) {
            int colg = wn0 + nt * 8 + (lane & 3) * 2;
            float b0 = bias[colg], b1 = bias[colg + 1];
#pragma unroll
            for (int half = 0; half < 2; half++) {
                int rr = r + half * 8;
                if (rr >= NN) continue;
                float2 v = make_float2(acc[mt][nt][half * 2]     + b0,
                                       acc[mt][nt][half * 2 + 1] + b1);
                *(float2*)(outp + (size_t)rr * NOUT + colg) = v;
            }
        }
    }
}

// ---------------- edge scoring ----------------------------------------------
__global__ void k_score(const void* ei, const float* __restrict__ refined,
                        float* __restrict__ out)
{
    int warp = threadIdx.x >> 5;
    int lane = threadIdx.x & 31;
    int e = blockIdx.x * 8 + warp;
    if (e >= NE) return;
    int s = edge_idx(ei, 0, e);
    int d = edge_idx(ei, 1, e);
    float4 va = ((const float4*)(refined + (size_t)s * D1))[lane];
    float4 vb = ((const float4*)(refined + (size_t)d * D1))[lane];
    float t = va.x * vb.x + va.y * vb.y + va.z * vb.z + va.w * vb.w;
#pragma unroll
    for (int o = 16; o > 0; o >>= 1) t += __shfl_xor_sync(0xFFFFFFFFu, t, o);
    if (lane == 0) out[e] = t;
}

// ---------------- launch -----------------------------------------------------
extern "C" void kernel_launch(void* const* d_in, const int* in_sizes, int n_in,
                              void* d_out, int out_size)
{
    const void*  ei    = d_in[0];
    const float* movie = (const float*)d_in[2];
    const float* user  = (const float*)d_in[3];
    const float* Wl1   = (const float*)d_in[4];
    const float* bl1   = (const float*)d_in[5];
    const float* Wr1   = (const float*)d_in[6];
    const float* Wl2   = (const float*)d_in[7];
    const float* bl2   = (const float*)d_in[8];
    const float* Wr2   = (const float*)d_in[9];

    float* out     = (float*)d_out;
    float* refined = out + NE;

    const int MB = (NN + 127) / 128;      // 1172
    const int SMEM1 = 2 * 18432;          // 36864
    const int SMEM2 = 2 * 36864;          // 73728

    cudaFuncSetAttribute(k_gemm1_f16, cudaFuncAttributeMaxDynamicSharedMemorySize, SMEM1);
    cudaFuncSetAttribute(k_gemm2_cp, cudaFuncAttributeMaxDynamicSharedMemorySize, SMEM2);

    k_detect<<<1, 256>>>(ei);
    k_split_w<<<512, 256>>>(Wl1, Wr1, Wl2, Wr2);
    k_split_x<<<(NN * 128 / 4 + 255) / 256, 256>>>(movie, user);
    k_zero<<<(NN + 255) / 256, 256>>>();
    k_count<<<(NE + 255) / 256, 256>>>(ei);
    k_scan1<<<(NN + 1023) / 1024, 1024>>>();
    k_scan2<<<1, 256>>>();
    k_scan3<<<(NN + 255) / 256, 256>>>();
    k_bucket<<<(NE + 255) / 256, 256>>>(ei);
    k_agg1<<<NN / 8, 256>>>(movie, user);
    k_gemm1_f16<<<dim3(MB, 2), 256, SMEM1>>>(bl1);
    k_agg2<<<NN / 8, 256>>>();
    k_gemm2_cp<<<MB, 256, SMEM2>>>(bl2, refined);
    k_score<<<(NE + 7) / 8, 256>>>(ei, refined, out);
}

// round 8
// speedup vs baseline: 3.3513x; 1.5014x over previous
#include <cuda_runtime.h>
#include <cuda_bf16.h>
#include <cuda_fp16.h>
#include <cstdint>
#include <cstddef>

#define NM 100000           // movies
#define NU 50000            // users
#define NN 150000           // total nodes
#define NE 500000           // edges
#define D1 128              // emb dim
#define D2 256              // hidden dim

// ---------------- scratch (device globals; no allocation allowed) ----------
__device__ int g_deg[NN];
__device__ int g_off[NN + 1];
__device__ int g_pos[NN];
__device__ int g_srcs[NE];
__device__ int g_bsum[256];
__device__ int g_is64;
// fp16 operands
__device__ __align__(256) __half g_xf[(size_t)NN * 128];     // split embeddings
__device__ __align__(256) __half g_a1f[(size_t)NN * 128];    // layer-1 aggregate
__device__ __align__(256) __half g_B1f[256 * 256];
__device__ __align__(256) __half g_hf[(size_t)NN * 256];     // hidden (fp16)
__device__ __align__(256) __half g_a2f[(size_t)NN * 256];    // layer-2 aggregate
__device__ __align__(256) __half g_B2f[512 * 128];
__device__ __align__(256) __half g_rf[(size_t)NN * 128];     // refined fp16 shadow

// ---------------- helpers ----------------------------------------------------
__device__ __forceinline__ int edge_idx(const void* ei, int which, int e) {
    if (g_is64) {
        const long long* p = (const long long*)ei;
        return (int)p[(size_t)which * NE + e];
    } else {
        const int* p = (const int*)ei;
        return p[(size_t)which * NE + e];
    }
}
__device__ __forceinline__ uint32_t pkh(float a, float b) {
    __half2 p = __floats2half2_rn(a, b);
    return *(uint32_t*)&p;
}
__device__ __forceinline__ void cpa16(uint32_t dst, const void* src) {
    asm volatile("cp.async.cg.shared.global [%0], [%1], 16;" :: "r"(dst), "l"(src));
}
__device__ __forceinline__ void cpa_commit() {
    asm volatile("cp.async.commit_group;" ::: "memory");
}
template <int N>
__device__ __forceinline__ void cpa_wait() {
    asm volatile("cp.async.wait_group %0;" :: "n"(N) : "memory");
}
__device__ __forceinline__ void ldsm4(uint32_t* r, uint32_t a) {
    asm volatile("ldmatrix.sync.aligned.m8n8.x4.shared.b16 {%0,%1,%2,%3}, [%4];"
                 : "=r"(r[0]), "=r"(r[1]), "=r"(r[2]), "=r"(r[3]) : "r"(a));
}
__device__ __forceinline__ void ldsm2t(uint32_t* r, uint32_t a) {
    asm volatile("ldmatrix.sync.aligned.m8n8.x2.trans.shared.b16 {%0,%1}, [%2];"
                 : "=r"(r[0]), "=r"(r[1]) : "r"(a));
}
__device__ __forceinline__ void mma_f16(float* c, const uint32_t* a, const uint32_t* b) {
    asm volatile(
        "mma.sync.aligned.m16n8k16.row.col.f32.f16.f16.f32 "
        "{%0,%1,%2,%3},{%4,%5,%6,%7},{%8,%9},{%0,%1,%2,%3};"
        : "+f"(c[0]), "+f"(c[1]), "+f"(c[2]), "+f"(c[3])
        : "r"(a[0]), "r"(a[1]), "r"(a[2]), "r"(a[3]), "r"(b[0]), "r"(b[1]));
}

// ---------------- small kernels ----------------------------------------------
__global__ void k_detect(const void* ei) {
    const long long* p = (const long long*)ei;
    int bad = 0;
    for (int i = threadIdx.x; i < 2048; i += blockDim.x) {
        long long v = p[i];
        if (v < 0 || v >= NN) bad = 1;
    }
    bad = __syncthreads_or(bad);
    if (threadIdx.x == 0) g_is64 = bad ? 0 : 1;
}

__global__ void k_zero() {
    int i = blockIdx.x * blockDim.x + threadIdx.x;
    if (i < NN) g_deg[i] = 0;
}

__global__ void k_count(const void* ei) {
    int e = blockIdx.x * blockDim.x + threadIdx.x;
    if (e < NE) atomicAdd(&g_deg[edge_idx(ei, 1, e)], 1);
}

__global__ void k_scan1() {
    __shared__ int s[1024];
    int i = blockIdx.x * 1024 + threadIdx.x;
    int v = (i < NN) ? g_deg[i] : 0;
    s[threadIdx.x] = v;
    __syncthreads();
#pragma unroll
    for (int off = 1; off < 1024; off <<= 1) {
        int t = (threadIdx.x >= off) ? s[threadIdx.x - off] : 0;
        __syncthreads();
        s[threadIdx.x] += t;
        __syncthreads();
    }
    if (i < NN) g_off[i] = s[threadIdx.x] - v;
    if (threadIdx.x == 1023) g_bsum[blockIdx.x] = s[1023];
}

__global__ void k_scan2() {
    __shared__ int s[256];
    const int NB = (NN + 1023) / 1024;
    int v = (threadIdx.x < NB) ? g_bsum[threadIdx.x] : 0;
    s[threadIdx.x] = v;
    __syncthreads();
#pragma unroll
    for (int off = 1; off < 256; off <<= 1) {
        int t = (threadIdx.x >= off) ? s[threadIdx.x - off] : 0;
        __syncthreads();
        s[threadIdx.x] += t;
        __syncthreads();
    }
    if (threadIdx.x < NB) g_bsum[threadIdx.x] = s[threadIdx.x] - v;
}

__global__ void k_scan3() {
    int i = blockIdx.x * blockDim.x + threadIdx.x;
    if (i < NN) {
        int val = g_off[i] + g_bsum[i >> 10];
        g_off[i] = val;
        g_pos[i] = val;
    }
    if (i == 0) g_off[NN] = NE;
}

__global__ void k_bucket(const void* ei) {
    int e = blockIdx.x * blockDim.x + threadIdx.x;
    if (e < NE) {
        int d = edge_idx(ei, 1, e);
        int p = atomicAdd(&g_pos[d], 1);
        g_srcs[p] = edge_idx(ei, 0, e);
    }
}

// weights -> fp16 (k-major layout kept)
__global__ void k_split_w(const float* __restrict__ Wl1, const float* __restrict__ Wr1,
                          const float* __restrict__ Wl2, const float* __restrict__ Wr2)
{
    int i = blockIdx.x * blockDim.x + threadIdx.x;
    if (i < 65536) {                       // B1 [256][256]
        float v = (i < 32768) ? Wl1[i] : Wr1[i - 32768];
        g_B1f[i] = __float2half(v);
    } else if (i < 131072) {               // B2 [512][128]
        int j = i - 65536;
        float v = (j < 32768) ? Wl2[j] : Wr2[j - 32768];
        g_B2f[j] = __float2half(v);
    }
}

// embeddings -> fp16
__global__ void k_split_x(const float* __restrict__ movie, const float* __restrict__ user) {
    int i = (blockIdx.x * blockDim.x + threadIdx.x) * 4;
    if (i >= NN * 128) return;
    int row = i >> 7, col = i & 127;
    const float* src = (row < NM) ? movie + (size_t)row * 128 + col
                                  : user + (size_t)(row - NM) * 128 + col;
    float4 v = *(const float4*)src;
    uint2 u = make_uint2(pkh(v.x, v.y), pkh(v.z, v.w));
    *(uint2*)(g_xf + i) = u;
}

// ---------------- aggregations (fp16 gather, fp32 accumulate) ----------------
__global__ void k_agg1() {
    int warp = threadIdx.x >> 5;
    int lane = threadIdx.x & 31;
    int node = blockIdx.x * 8 + warp;
    if (node >= NN) return;
    int beg = g_off[node], end = g_off[node + 1];
    float a0 = 0.f, a1 = 0.f, a2 = 0.f, a3 = 0.f;
    for (int e = beg; e < end; e++) {
        int s = g_srcs[e];
        uint2 v = ((const uint2*)(g_xf + (size_t)s * 128))[lane];
        float2 f0 = __half22float2(*(__half2*)&v.x);
        float2 f1 = __half22float2(*(__half2*)&v.y);
        a0 += f0.x; a1 += f0.y; a2 += f1.x; a3 += f1.y;
    }
    int cnt = end - beg;
    float inv = 1.0f / (float)(cnt > 0 ? cnt : 1);
    uint2 u = make_uint2(pkh(a0 * inv, a1 * inv), pkh(a2 * inv, a3 * inv));
    *(uint2*)(g_a1f + (size_t)node * 128 + lane * 4) = u;
}

__global__ void k_agg2() {
    int warp = threadIdx.x >> 5;
    int lane = threadIdx.x & 31;
    int node = blockIdx.x * 8 + warp;
    if (node >= NN) return;
    int beg = g_off[node], end = g_off[node + 1];
    float a[8];
#pragma unroll
    for (int i = 0; i < 8; i++) a[i] = 0.f;
    for (int e = beg; e < end; e++) {
        int s = g_srcs[e];
        uint4 v = ((const uint4*)(g_hf + (size_t)s * 256))[lane];
        const uint32_t* vp = (const uint32_t*)&v;
#pragma unroll
        for (int i = 0; i < 4; i++) {
            float2 f = __half22float2(*(const __half2*)&vp[i]);
            a[2 * i]     += f.x;
            a[2 * i + 1] += f.y;
        }
    }
    int cnt = end - beg;
    float inv = 1.0f / (float)(cnt > 0 ? cnt : 1);
    uint32_t u[4];
#pragma unroll
    for (int i = 0; i < 4; i++)
        u[i] = pkh(a[2 * i] * inv, a[2 * i + 1] * inv);
    *(uint4*)(g_a2f + (size_t)node * 256 + lane * 8) = *(uint4*)u;
}

// ---------------- fp16 HMMA GEMM (pipelined), shared for both layers ---------
// LAYER 1: A=[a1|x] [NN,256]  B1[256,256] -> g_hf = relu(A@B1 + b1), grid (MB,2)
// LAYER 2: A=[a2|h] [NN,512]  B2[512,128] -> refined fp32 + g_rf,    grid (MB,1)
// BM=128 BN=128 BK=32, 256 thr, warp tile 64x32. Stage 18432B x 2.
template <int LAYER>
__global__ void __launch_bounds__(256, 2) k_gemm_f16(
    const float* __restrict__ bias, float* __restrict__ outp)
{
    constexpr int KTOT = (LAYER == 1) ? 256 : 512;
    constexpr int KA   = (LAYER == 1) ? 128 : 256;
    constexpr int NCH  = KTOT / 32;
    constexpr int STG  = 18432;

    extern __shared__ char smr[];
    uint32_t sm0 = (uint32_t)__cvta_generic_to_shared(smr);

    int tid = threadIdx.x, lane = tid & 31, warp = tid >> 5;
    int wm0 = (warp >> 2) * 64, wn0 = (warp & 3) * 32;
    int row0 = blockIdx.x * 128, n0 = blockIdx.y * 128;

    float acc[4][4][4];
#pragma unroll
    for (int i = 0; i < 4; i++)
#pragma unroll
        for (int j = 0; j < 4; j++)
#pragma unroll
            for (int q = 0; q < 4; q++) acc[i][j][q] = 0.f;

    auto stage = [&](int ch, int s) {
        uint32_t sb = sm0 + (uint32_t)(s * STG);
        // A: 128 rows x 32 k fp16 (64B/row, 80B stride), 512 x 16B chunks
#pragma unroll
        for (int i = 0; i < 2; i++) {
            int idx = tid + i * 256;
            int row = idx >> 2, c = idx & 3;
            int grow = row0 + row;
            if (grow >= NN) grow = 0;
            int kk = ch * 32 + c * 8;
            const __half* src;
            if (LAYER == 1)
                src = (kk < KA) ? g_a1f + (size_t)grow * 128 + kk
                                : g_xf  + (size_t)grow * 128 + (kk - KA);
            else
                src = (kk < KA) ? g_a2f + (size_t)grow * 256 + kk
                                : g_hf  + (size_t)grow * 256 + (kk - KA);
            cpa16(sb + (uint32_t)(row * 80 + c * 16), src);
        }
        // B: 32 k x 128 n fp16, XOR-swizzled, 512 x 16B chunks
#pragma unroll
        for (int i = 0; i < 2; i++) {
            int idx = tid + i * 256;
            int k = idx >> 4, c = idx & 15;
            int kg = ch * 32 + k;
            const __half* src = (LAYER == 1)
                ? g_B1f + (size_t)kg * 256 + n0 + c * 8
                : g_B2f + (size_t)kg * 128 + c * 8;
            cpa16(sb + 10240u + (uint32_t)(k * 256 + ((c ^ (k & 7)) << 4)), src);
        }
    };

    stage(0, 0);
    cpa_commit();

    for (int ch = 0; ch < NCH; ch++) {
        int s = ch & 1;
        if (ch + 1 < NCH) {
            stage(ch + 1, (ch + 1) & 1);
            cpa_commit();
            cpa_wait<1>();
        } else {
            cpa_wait<0>();
        }
        __syncthreads();

        uint32_t ab = sm0 + (uint32_t)(s * STG);
        uint32_t bb = ab + 10240;
#pragma unroll
        for (int ks = 0; ks < 2; ks++) {
            uint32_t aF[4][4];
#pragma unroll
            for (int mt = 0; mt < 4; mt++) {
                int r  = wm0 + mt * 16 + (lane & 15);
                int kc = ks * 16 + ((lane >> 4) << 3);
                ldsm4(aF[mt], ab + (uint32_t)(r * 80 + kc * 2));
            }
#pragma unroll
            for (int nt = 0; nt < 4; nt++) {
                int kk = ks * 16 + (lane & 15);
                int cc = (wn0 + nt * 8) >> 3;
                uint32_t bF[2];
                ldsm2t(bF, bb + (uint32_t)(kk * 256 + ((cc ^ (kk & 7)) << 4)));
#pragma unroll
                for (int mt = 0; mt < 4; mt++)
                    mma_f16(acc[mt][nt], aF[mt], bF);
            }
        }
        __syncthreads();
    }

    // ---- epilogue ----
#pragma unroll
    for (int mt = 0; mt < 4; mt++) {
        int r = row0 + wm0 + mt * 16 + (lane >> 2);
#pragma unroll
        for (int nt = 0; nt < 4; nt++) {
            int colg = n0 + wn0 + nt * 8 + (lane & 3) * 2;
            float b0 = bias[colg], b1 = bias[colg + 1];
#pragma unroll
            for (int half = 0; half < 2; half++) {
                int rr = r + half * 8;
                if (rr >= NN) continue;
                float vx = acc[mt][nt][half * 2]     + b0;
                float vy = acc[mt][nt][half * 2 + 1] + b1;
                if (LAYER == 1) {
                    vx = fmaxf(vx, 0.f);
                    vy = fmaxf(vy, 0.f);
                    *(uint32_t*)(g_hf + (size_t)rr * 256 + colg) = pkh(vx, vy);
                } else {
                    *(float2*)(outp + (size_t)rr * 128 + colg) = make_float2(vx, vy);
                    *(uint32_t*)(g_rf + (size_t)rr * 128 + colg) = pkh(vx, vy);
                }
            }
        }
    }
}

// ---------------- edge scoring (fp16 gather, fp32 dot) -----------------------
__global__ void k_score(const void* ei, float* __restrict__ out)
{
    int warp = threadIdx.x >> 5;
    int lane = threadIdx.x & 31;
    int e = blockIdx.x * 8 + warp;
    if (e >= NE) return;
    int s = edge_idx(ei, 0, e);
    int d = edge_idx(ei, 1, e);
    uint2 va = ((const uint2*)(g_rf + (size_t)s * D1))[lane];
    uint2 vb = ((const uint2*)(g_rf + (size_t)d * D1))[lane];
    float2 a0 = __half22float2(*(__half2*)&va.x);
    float2 a1 = __half22float2(*(__half2*)&va.y);
    float2 b0 = __half22float2(*(__half2*)&vb.x);
    float2 b1 = __half22float2(*(__half2*)&vb.y);
    float t = a0.x * b0.x + a0.y * b0.y + a1.x * b1.x + a1.y * b1.y;
#pragma unroll
    for (int o = 16; o > 0; o >>= 1) t += __shfl_xor_sync(0xFFFFFFFFu, t, o);
    if (lane == 0) out[e] = t;
}

// ---------------- launch -----------------------------------------------------
extern "C" void kernel_launch(void* const* d_in, const int* in_sizes, int n_in,
                              void* d_out, int out_size)
{
    const void*  ei    = d_in[0];
    const float* movie = (const float*)d_in[2];
    const float* user  = (const float*)d_in[3];
    const float* Wl1   = (const float*)d_in[4];
    const float* bl1   = (const float*)d_in[5];
    const float* Wr1   = (const float*)d_in[6];
    const float* Wl2   = (const float*)d_in[7];
    const float* bl2   = (const float*)d_in[8];
    const float* Wr2   = (const float*)d_in[9];

    float* out     = (float*)d_out;
    float* refined = out + NE;

    const int MB = (NN + 127) / 128;      // 1172
    const int SMEM = 2 * 18432;           // 36864

    cudaFuncSetAttribute(k_gemm_f16<1>, cudaFuncAttributeMaxDynamicSharedMemorySize, SMEM);
    cudaFuncSetAttribute(k_gemm_f16<2>, cudaFuncAttributeMaxDynamicSharedMemorySize, SMEM);

    k_detect<<<1, 256>>>(ei);
    k_split_w<<<512, 256>>>(Wl1, Wr1, Wl2, Wr2);
    k_split_x<<<(NN * 128 / 4 + 255) / 256, 256>>>(movie, user);
    k_zero<<<(NN + 255) / 256, 256>>>();
    k_count<<<(NE + 255) / 256, 256>>>(ei);
    k_scan1<<<(NN + 1023) / 1024, 1024>>>();
    k_scan2<<<1, 256>>>();
    k_scan3<<<(NN + 255) / 256, 256>>>();
    k_bucket<<<(NE + 255) / 256, 256>>>(ei);
    k_agg1<<<NN / 8, 256>>>();
    k_gemm_f16<1><<<dim3(MB, 2), 256, SMEM>>>(bl1, nullptr);
    k_agg2<<<NN / 8, 256>>>();
    k_gemm_f16<2><<<dim3(MB, 1), 256, SMEM>>>(bl2, refined);
    k_score<<<(NE + 7) / 8, 256>>>(ei, out);
}

// round 9
// speedup vs baseline: 3.5090x; 1.0471x over previous
#include <cuda_runtime.h>
#include <cuda_bf16.h>
#include <cuda_fp16.h>
#include <cstdint>
#include <cstddef>

#define NM 100000           // movies
#define NU 50000            // users
#define NN 150000           // total nodes
#define NE 500000           // edges
#define D1 128              // emb dim
#define D2 256              // hidden dim

// ---------------- scratch (device globals; no allocation allowed) ----------
__device__ int g_deg[NN];
__device__ int g_off[NN + 1];
__device__ int g_pos[NN];
__device__ int g_srcs[NE];
__device__ int g_eids[NE];
__device__ int g_bsum[256];
__device__ int g_is64;
// fp16 operands
__device__ __align__(256) __half g_xf[(size_t)NN * 128];     // embeddings fp16
__device__ __align__(256) __half g_a1f[(size_t)NN * 128];    // layer-1 aggregate
__device__ __align__(256) __half g_B1f[256 * 256];           // [Wl1;Wr1] k-major
__device__ __align__(256) __half g_hf[(size_t)NN * 256];     // hidden fp16
__device__ __align__(256) __half g_B2f[256 * 256];           // [Wl2|Wr2] n-concat
__device__ __align__(256) __half g_pf[(size_t)NN * 128];     // p = h@Wl2 (fp16)
__device__ __align__(256) float  g_q[(size_t)NN * 128];      // q = h@Wr2 + b (fp32)
__device__ __align__(256) __half g_rf[(size_t)NN * 128];     // refined fp16 shadow

// ---------------- helpers ----------------------------------------------------
__device__ __forceinline__ int edge_idx(const void* ei, int which, int e) {
    if (g_is64) {
        const long long* p = (const long long*)ei;
        return (int)p[(size_t)which * NE + e];
    } else {
        const int* p = (const int*)ei;
        return p[(size_t)which * NE + e];
    }
}
__device__ __forceinline__ uint32_t pkh(float a, float b) {
    __half2 p = __floats2half2_rn(a, b);
    return *(uint32_t*)&p;
}
__device__ __forceinline__ void cpa16(uint32_t dst, const void* src) {
    asm volatile("cp.async.cg.shared.global [%0], [%1], 16;" :: "r"(dst), "l"(src));
}
__device__ __forceinline__ void cpa_commit() {
    asm volatile("cp.async.commit_group;" ::: "memory");
}
template <int N>
__device__ __forceinline__ void cpa_wait() {
    asm volatile("cp.async.wait_group %0;" :: "n"(N) : "memory");
}
__device__ __forceinline__ void ldsm4(uint32_t* r, uint32_t a) {
    asm volatile("ldmatrix.sync.aligned.m8n8.x4.shared.b16 {%0,%1,%2,%3}, [%4];"
                 : "=r"(r[0]), "=r"(r[1]), "=r"(r[2]), "=r"(r[3]) : "r"(a));
}
__device__ __forceinline__ void ldsm2t(uint32_t* r, uint32_t a) {
    asm volatile("ldmatrix.sync.aligned.m8n8.x2.trans.shared.b16 {%0,%1}, [%2];"
                 : "=r"(r[0]), "=r"(r[1]) : "r"(a));
}
__device__ __forceinline__ void mma_f16(float* c, const uint32_t* a, const uint32_t* b) {
    asm volatile(
        "mma.sync.aligned.m16n8k16.row.col.f32.f16.f16.f32 "
        "{%0,%1,%2,%3},{%4,%5,%6,%7},{%8,%9},{%0,%1,%2,%3};"
        : "+f"(c[0]), "+f"(c[1]), "+f"(c[2]), "+f"(c[3])
        : "r"(a[0]), "r"(a[1]), "r"(a[2]), "r"(a[3]), "r"(b[0]), "r"(b[1]));
}

// ---------------- fused prep: detect + zero deg + split weights + split x ----
__global__ void k_prep(const void* ei,
                       const float* __restrict__ movie, const float* __restrict__ user,
                       const float* __restrict__ Wl1, const float* __restrict__ Wr1,
                       const float* __restrict__ Wl2, const float* __restrict__ Wr2)
{
    int gid = blockIdx.x * 256 + threadIdx.x;
    if (blockIdx.x == 0) {
        const long long* p = (const long long*)ei;
        int bad = 0;
        for (int i = threadIdx.x; i < 2048; i += 256) {
            long long v = p[i];
            if (v < 0 || v >= NN) bad = 1;
        }
        bad = __syncthreads_or(bad);
        if (threadIdx.x == 0) g_is64 = bad ? 0 : 1;
    }
    if (gid < NN) g_deg[gid] = 0;
    if (gid < 65536) {                       // B1 [k=256][n=256] = [Wl1;Wr1]
        float v = (gid < 32768) ? Wl1[gid] : Wr1[gid - 32768];
        g_B1f[gid] = __float2half(v);
    } else if (gid < 131072) {               // B2 [k=256][n=256] = [Wl2|Wr2]
        int j = gid - 65536;
        int k = j >> 8, n = j & 255;
        float v = (n < 128) ? Wl2[(size_t)k * 128 + n]
                            : Wr2[(size_t)k * 128 + (n - 128)];
        g_B2f[j] = __float2half(v);
    }
    int i = gid * 4;
    if (i < NN * 128) {
        int row = i >> 7, col = i & 127;
        const float* src = (row < NM) ? movie + (size_t)row * 128 + col
                                      : user + (size_t)(row - NM) * 128 + col;
        float4 v = *(const float4*)src;
        *(uint2*)(g_xf + i) = make_uint2(pkh(v.x, v.y), pkh(v.z, v.w));
    }
}

// ---------------- CSR construction -------------------------------------------
__global__ void k_count(const void* ei) {
    int e = blockIdx.x * blockDim.x + threadIdx.x;
    if (e < NE) atomicAdd(&g_deg[edge_idx(ei, 1, e)], 1);
}

__global__ void k_scan1() {
    __shared__ int s[1024];
    int i = blockIdx.x * 1024 + threadIdx.x;
    int v = (i < NN) ? g_deg[i] : 0;
    s[threadIdx.x] = v;
    __syncthreads();
#pragma unroll
    for (int off = 1; off < 1024; off <<= 1) {
        int t = (threadIdx.x >= off) ? s[threadIdx.x - off] : 0;
        __syncthreads();
        s[threadIdx.x] += t;
        __syncthreads();
    }
    if (i < NN) g_off[i] = s[threadIdx.x] - v;
    if (threadIdx.x == 1023) g_bsum[blockIdx.x] = s[1023];
}

__global__ void k_scan2() {
    __shared__ int s[256];
    const int NB = (NN + 1023) / 1024;
    int v = (threadIdx.x < NB) ? g_bsum[threadIdx.x] : 0;
    s[threadIdx.x] = v;
    __syncthreads();
#pragma unroll
    for (int off = 1; off < 256; off <<= 1) {
        int t = (threadIdx.x >= off) ? s[threadIdx.x - off] : 0;
        __syncthreads();
        s[threadIdx.x] += t;
        __syncthreads();
    }
    if (threadIdx.x < NB) g_bsum[threadIdx.x] = s[threadIdx.x] - v;
}

__global__ void k_scan3() {
    int i = blockIdx.x * blockDim.x + threadIdx.x;
    if (i < NN) {
        int val = g_off[i] + g_bsum[i >> 10];
        g_off[i] = val;
        g_pos[i] = val;
    }
    if (i == 0) g_off[NN] = NE;
}

__global__ void k_bucket(const void* ei) {
    int e = blockIdx.x * blockDim.x + threadIdx.x;
    if (e < NE) {
        int d = edge_idx(ei, 1, e);
        int p = atomicAdd(&g_pos[d], 1);
        g_srcs[p] = edge_idx(ei, 0, e);
        g_eids[p] = e;
    }
}

// ---------------- layer-1 aggregation (fp16 gather, fp32 acc) ----------------
__global__ void k_agg1() {
    int warp = threadIdx.x >> 5;
    int lane = threadIdx.x & 31;
    int node = blockIdx.x * 8 + warp;
    if (node >= NN) return;
    int beg = g_off[node], end = g_off[node + 1];
    float a0 = 0.f, a1 = 0.f, a2 = 0.f, a3 = 0.f;
    for (int e = beg; e < end; e++) {
        int s = g_srcs[e];
        uint2 v = ((const uint2*)(g_xf + (size_t)s * 128))[lane];
        float2 f0 = __half22float2(*(__half2*)&v.x);
        float2 f1 = __half22float2(*(__half2*)&v.y);
        a0 += f0.x; a1 += f0.y; a2 += f1.x; a3 += f1.y;
    }
    int cnt = end - beg;
    float inv = 1.0f / (float)(cnt > 0 ? cnt : 1);
    uint2 u = make_uint2(pkh(a0 * inv, a1 * inv), pkh(a2 * inv, a3 * inv));
    *(uint2*)(g_a1f + (size_t)node * 128 + lane * 4) = u;
}

// ---------------- fp16 HMMA GEMM (pipelined) ---------------------------------
// LAYER 1: A=[a1|x] [NN,256]  B1[256,256] -> g_hf = relu(A@B1 + b1)
// LAYER 2: A=h      [NN,256]  B2[256,256] -> ny0: g_pf fp16 (h@Wl2)
//                                            ny1: g_q  fp32 (h@Wr2 + b2)
// BM=128 BN=128 BK=32, 256 thr, warp tile 64x32. Stage 18432B x 2.
template <int LAYER>
__global__ void __launch_bounds__(256, 2) k_gemm_f16(const float* __restrict__ bias)
{
    constexpr int NCH = 8;               // K=256
    constexpr int STG = 18432;

    extern __shared__ char smr[];
    uint32_t sm0 = (uint32_t)__cvta_generic_to_shared(smr);

    int tid = threadIdx.x, lane = tid & 31, warp = tid >> 5;
    int wm0 = (warp >> 2) * 64, wn0 = (warp & 3) * 32;
    int row0 = blockIdx.x * 128, n0 = blockIdx.y * 128;

    float acc[4][4][4];
#pragma unroll
    for (int i = 0; i < 4; i++)
#pragma unroll
        for (int j = 0; j < 4; j++)
#pragma unroll
            for (int q = 0; q < 4; q++) acc[i][j][q] = 0.f;

    auto stage = [&](int ch, int s) {
        uint32_t sb = sm0 + (uint32_t)(s * STG);
#pragma unroll
        for (int i = 0; i < 2; i++) {
            int idx = tid + i * 256;
            int row = idx >> 2, c = idx & 3;
            int grow = row0 + row;
            if (grow >= NN) grow = 0;
            int kk = ch * 32 + c * 8;
            const __half* src;
            if (LAYER == 1)
                src = (kk < 128) ? g_a1f + (size_t)grow * 128 + kk
                                 : g_xf  + (size_t)grow * 128 + (kk - 128);
            else
                src = g_hf + (size_t)grow * 256 + kk;
            cpa16(sb + (uint32_t)(row * 80 + c * 16), src);
        }
#pragma unroll
        for (int i = 0; i < 2; i++) {
            int idx = tid + i * 256;
            int k = idx >> 4, c = idx & 15;
            int kg = ch * 32 + k;
            const __half* src = (LAYER == 1)
                ? g_B1f + (size_t)kg * 256 + n0 + c * 8
                : g_B2f + (size_t)kg * 256 + n0 + c * 8;
            cpa16(sb + 10240u + (uint32_t)(k * 256 + ((c ^ (k & 7)) << 4)), src);
        }
    };

    stage(0, 0);
    cpa_commit();

    for (int ch = 0; ch < NCH; ch++) {
        int s = ch & 1;
        if (ch + 1 < NCH) {
            stage(ch + 1, (ch + 1) & 1);
            cpa_commit();
            cpa_wait<1>();
        } else {
            cpa_wait<0>();
        }
        __syncthreads();

        uint32_t ab = sm0 + (uint32_t)(s * STG);
        uint32_t bb = ab + 10240;
#pragma unroll
        for (int ks = 0; ks < 2; ks++) {
            uint32_t aF[4][4];
#pragma unroll
            for (int mt = 0; mt < 4; mt++) {
                int r  = wm0 + mt * 16 + (lane & 15);
                int kc = ks * 16 + ((lane >> 4) << 3);
                ldsm4(aF[mt], ab + (uint32_t)(r * 80 + kc * 2));
            }
#pragma unroll
            for (int nt = 0; nt < 4; nt++) {
                int kk = ks * 16 + (lane & 15);
                int cc = (wn0 + nt * 8) >> 3;
                uint32_t bF[2];
                ldsm2t(bF, bb + (uint32_t)(kk * 256 + ((cc ^ (kk & 7)) << 4)));
#pragma unroll
                for (int mt = 0; mt < 4; mt++)
                    mma_f16(acc[mt][nt], aF[mt], bF);
            }
        }
        __syncthreads();
    }

    // ---- epilogue ----
#pragma unroll
    for (int mt = 0; mt < 4; mt++) {
        int r = row0 + wm0 + mt * 16 + (lane >> 2);
#pragma unroll
        for (int nt = 0; nt < 4; nt++) {
            int colg = n0 + wn0 + nt * 8 + (lane & 3) * 2;
            float b0 = 0.f, b1 = 0.f;
            if (LAYER == 1) { b0 = bias[colg]; b1 = bias[colg + 1]; }
            else if (n0 == 128) { b0 = bias[colg - 128]; b1 = bias[colg - 127]; }
#pragma unroll
            for (int half = 0; half < 2; half++) {
                int rr = r + half * 8;
                if (rr >= NN) continue;
                float vx = acc[mt][nt][half * 2]     + b0;
                float vy = acc[mt][nt][half * 2 + 1] + b1;
                if (LAYER == 1) {
                    vx = fmaxf(vx, 0.f);
                    vy = fmaxf(vy, 0.f);
                    *(uint32_t*)(g_hf + (size_t)rr * 256 + colg) = pkh(vx, vy);
                } else if (n0 == 0) {
                    *(uint32_t*)(g_pf + (size_t)rr * 128 + colg) = pkh(vx, vy);
                } else {
                    *(float2*)(g_q + (size_t)rr * 128 + (colg - 128)) =
                        make_float2(vx, vy);
                }
            }
        }
    }
}

// ---------------- layer-2: refined = mean(p[srcs]) + q  ----------------------
__global__ void k_agg2f(float* __restrict__ refined) {
    int warp = threadIdx.x >> 5;
    int lane = threadIdx.x & 31;
    int node = blockIdx.x * 8 + warp;
    if (node >= NN) return;
    int beg = g_off[node], end = g_off[node + 1];
    float a0 = 0.f, a1 = 0.f, a2 = 0.f, a3 = 0.f;
    for (int e = beg; e < end; e++) {
        int s = g_srcs[e];
        uint2 v = ((const uint2*)(g_pf + (size_t)s * 128))[lane];
        float2 f0 = __half22float2(*(__half2*)&v.x);
        float2 f1 = __half22float2(*(__half2*)&v.y);
        a0 += f0.x; a1 += f0.y; a2 += f1.x; a3 += f1.y;
    }
    int cnt = end - beg;
    float inv = 1.0f / (float)(cnt > 0 ? cnt : 1);
    float4 qv = ((const float4*)(g_q + (size_t)node * 128))[lane];
    float4 o = make_float4(a0 * inv + qv.x, a1 * inv + qv.y,
                           a2 * inv + qv.z, a3 * inv + qv.w);
    ((float4*)(refined + (size_t)node * 128))[lane] = o;
    *(uint2*)(g_rf + (size_t)node * 128 + lane * 4) =
        make_uint2(pkh(o.x, o.y), pkh(o.z, o.w));
}

// ---------------- CSR-order edge scoring -------------------------------------
__global__ void k_score(float* __restrict__ out) {
    int warp = threadIdx.x >> 5;
    int lane = threadIdx.x & 31;
    int node = blockIdx.x * 8 + warp;
    if (node >= NN) return;
    int beg = g_off[node], end = g_off[node + 1];
    if (beg == end) return;
    uint2 va = ((const uint2*)(g_rf + (size_t)node * 128))[lane];
    float2 d0 = __half22float2(*(__half2*)&va.x);
    float2 d1 = __half22float2(*(__half2*)&va.y);
    for (int e = beg; e < end; e++) {
        int s = g_srcs[e];
        uint2 vb = ((const uint2*)(g_rf + (size_t)s * 128))[lane];
        float2 s0 = __half22float2(*(__half2*)&vb.x);
        float2 s1 = __half22float2(*(__half2*)&vb.y);
        float t = d0.x * s0.x + d0.y * s0.y + d1.x * s1.x + d1.y * s1.y;
#pragma unroll
        for (int o = 16; o > 0; o >>= 1) t += __shfl_xor_sync(0xFFFFFFFFu, t, o);
        if (lane == 0) out[g_eids[e]] = t;
    }
}

// ---------------- launch -----------------------------------------------------
extern "C" void kernel_launch(void* const* d_in, const int* in_sizes, int n_in,
                              void* d_out, int out_size)
{
    const void*  ei    = d_in[0];
    const float* movie = (const float*)d_in[2];
    const float* user  = (const float*)d_in[3];
    const float* Wl1   = (const float*)d_in[4];
    const float* bl1   = (const float*)d_in[5];
    const float* Wr1   = (const float*)d_in[6];
    const float* Wl2   = (const float*)d_in[7];
    const float* bl2   = (const float*)d_in[8];
    const float* Wr2   = (const float*)d_in[9];

    float* out     = (float*)d_out;
    float* refined = out + NE;

    const int MB = (NN + 127) / 128;      // 1172
    const int SMEM = 2 * 18432;           // 36864
    const int PREP_B = (NN * 128 / 4 + 255) / 256;   // 18750

    cudaFuncSetAttribute(k_gemm_f16<1>, cudaFuncAttributeMaxDynamicSharedMemorySize, SMEM);
    cudaFuncSetAttribute(k_gemm_f16<2>, cudaFuncAttributeMaxDynamicSharedMemorySize, SMEM);

    k_prep<<<PREP_B, 256>>>(ei, movie, user, Wl1, Wr1, Wl2, Wr2);
    k_count<<<(NE + 255) / 256, 256>>>(ei);
    k_scan1<<<(NN + 1023) / 1024, 1024>>>();
    k_scan2<<<1, 256>>>();
    k_scan3<<<(NN + 255) / 256, 256>>>();
    k_bucket<<<(NE + 255) / 256, 256>>>(ei);
    k_agg1<<<(NN + 7) / 8, 256>>>();
    k_gemm_f16<1><<<dim3(MB, 2), 256, SMEM>>>(bl1);
    k_gemm_f16<2><<<dim3(MB, 2), 256, SMEM>>>(bl2);
    k_agg2f<<<(NN + 7) / 8, 256>>>(refined);
    k_score<<<(NN + 7) / 8, 256>>>(out);
}

// round 10
// speedup vs baseline: 3.6630x; 1.0439x over previous
#include <cuda_runtime.h>
#include <cuda_bf16.h>
#include <cuda_fp16.h>
#include <cstdint>
#include <cstddef>

#define NM 100000           // movies
#define NU 50000            // users
#define NN 150000           // total nodes
#define NE 500000           // edges
#define D1 128              // emb dim
#define D2 256              // hidden dim

// ---------------- scratch (device globals; no allocation allowed) ----------
__device__ int g_deg[NN];
__device__ int g_off[NN + 1];
__device__ int g_pos[NN];
__device__ int g_srcs[NE];
__device__ int g_eids[NE];
__device__ int g_bsum[256];
__device__ int g_is64;
// fp16 operands
__device__ __align__(256) __half g_xf[(size_t)NN * 128];     // embeddings fp16
__device__ __align__(256) __half g_a1f[(size_t)NN * 128];    // layer-1 aggregate
__device__ __align__(256) __half g_B1f[256 * 256];           // [Wl1;Wr1] k-major
__device__ __align__(256) __half g_B2f[256 * 256];           // [Wl2|Wr2] n-concat
__device__ __align__(256) __half g_pf[(size_t)NN * 128];     // p = h@Wl2 (fp16)
__device__ __align__(256) __half g_qf[(size_t)NN * 128];     // q = h@Wr2+b2 (fp16)
__device__ __align__(256) __half g_rf[(size_t)NN * 128];     // refined fp16 shadow

// ---------------- helpers ----------------------------------------------------
__device__ __forceinline__ int edge_idx(const void* ei, int which, int e) {
    if (g_is64) {
        const long long* p = (const long long*)ei;
        return (int)p[(size_t)which * NE + e];
    } else {
        const int* p = (const int*)ei;
        return p[(size_t)which * NE + e];
    }
}
__device__ __forceinline__ uint32_t pkh(float a, float b) {
    __half2 p = __floats2half2_rn(a, b);
    return *(uint32_t*)&p;
}
__device__ __forceinline__ void cpa16(uint32_t dst, const void* src) {
    asm volatile("cp.async.cg.shared.global [%0], [%1], 16;" :: "r"(dst), "l"(src));
}
__device__ __forceinline__ void cpa_commit() {
    asm volatile("cp.async.commit_group;" ::: "memory");
}
template <int N>
__device__ __forceinline__ void cpa_wait() {
    asm volatile("cp.async.wait_group %0;" :: "n"(N) : "memory");
}
__device__ __forceinline__ void ldsm4(uint32_t* r, uint32_t a) {
    asm volatile("ldmatrix.sync.aligned.m8n8.x4.shared.b16 {%0,%1,%2,%3}, [%4];"
                 : "=r"(r[0]), "=r"(r[1]), "=r"(r[2]), "=r"(r[3]) : "r"(a));
}
__device__ __forceinline__ void ldsm2t(uint32_t* r, uint32_t a) {
    asm volatile("ldmatrix.sync.aligned.m8n8.x2.trans.shared.b16 {%0,%1}, [%2];"
                 : "=r"(r[0]), "=r"(r[1]) : "r"(a));
}
__device__ __forceinline__ void mma_f16(float* c, const uint32_t* a, const uint32_t* b) {
    asm volatile(
        "mma.sync.aligned.m16n8k16.row.col.f32.f16.f16.f32 "
        "{%0,%1,%2,%3},{%4,%5,%6,%7},{%8,%9},{%0,%1,%2,%3};"
        : "+f"(c[0]), "+f"(c[1]), "+f"(c[2]), "+f"(c[3])
        : "r"(a[0]), "r"(a[1]), "r"(a[2]), "r"(a[3]), "r"(b[0]), "r"(b[1]));
}

// ---------------- fused prep: detect + zero deg + split weights + split x ----
__global__ void k_prep(const void* ei,
                       const float* __restrict__ movie, const float* __restrict__ user,
                       const float* __restrict__ Wl1, const float* __restrict__ Wr1,
                       const float* __restrict__ Wl2, const float* __restrict__ Wr2)
{
    int gid = blockIdx.x * 256 + threadIdx.x;
    if (blockIdx.x == 0) {
        const long long* p = (const long long*)ei;
        int bad = 0;
        for (int i = threadIdx.x; i < 2048; i += 256) {
            long long v = p[i];
            if (v < 0 || v >= NN) bad = 1;
        }
        bad = __syncthreads_or(bad);
        if (threadIdx.x == 0) g_is64 = bad ? 0 : 1;
    }
    if (gid < NN) g_deg[gid] = 0;
    if (gid < 65536) {                       // B1 [k=256][n=256] = [Wl1;Wr1]
        float v = (gid < 32768) ? Wl1[gid] : Wr1[gid - 32768];
        g_B1f[gid] = __float2half(v);
    } else if (gid < 131072) {               // B2 [k=256][n=256] = [Wl2|Wr2]
        int j = gid - 65536;
        int k = j >> 8, n = j & 255;
        float v = (n < 128) ? Wl2[(size_t)k * 128 + n]
                            : Wr2[(size_t)k * 128 + (n - 128)];
        g_B2f[j] = __float2half(v);
    }
    int i = gid * 4;
    if (i < NN * 128) {
        int row = i >> 7, col = i & 127;
        const float* src = (row < NM) ? movie + (size_t)row * 128 + col
                                      : user + (size_t)(row - NM) * 128 + col;
        float4 v = *(const float4*)src;
        *(uint2*)(g_xf + i) = make_uint2(pkh(v.x, v.y), pkh(v.z, v.w));
    }
}

// ---------------- CSR construction -------------------------------------------
__global__ void k_count(const void* ei) {
    int e = blockIdx.x * blockDim.x + threadIdx.x;
    if (e < NE) atomicAdd(&g_deg[edge_idx(ei, 1, e)], 1);
}

__global__ void k_scan1() {
    __shared__ int s[1024];
    int i = blockIdx.x * 1024 + threadIdx.x;
    int v = (i < NN) ? g_deg[i] : 0;
    s[threadIdx.x] = v;
    __syncthreads();
#pragma unroll
    for (int off = 1; off < 1024; off <<= 1) {
        int t = (threadIdx.x >= off) ? s[threadIdx.x - off] : 0;
        __syncthreads();
        s[threadIdx.x] += t;
        __syncthreads();
    }
    if (i < NN) g_off[i] = s[threadIdx.x] - v;
    if (threadIdx.x == 1023) g_bsum[blockIdx.x] = s[1023];
}

__global__ void k_scan2() {
    __shared__ int s[256];
    const int NB = (NN + 1023) / 1024;
    int v = (threadIdx.x < NB) ? g_bsum[threadIdx.x] : 0;
    s[threadIdx.x] = v;
    __syncthreads();
#pragma unroll
    for (int off = 1; off < 256; off <<= 1) {
        int t = (threadIdx.x >= off) ? s[threadIdx.x - off] : 0;
        __syncthreads();
        s[threadIdx.x] += t;
        __syncthreads();
    }
    if (threadIdx.x < NB) g_bsum[threadIdx.x] = s[threadIdx.x] - v;
}

__global__ void k_scan3() {
    int i = blockIdx.x * blockDim.x + threadIdx.x;
    if (i < NN) {
        int val = g_off[i] + g_bsum[i >> 10];
        g_off[i] = val;
        g_pos[i] = val;
    }
    if (i == 0) g_off[NN] = NE;
}

__global__ void k_bucket(const void* ei) {
    int e = blockIdx.x * blockDim.x + threadIdx.x;
    if (e < NE) {
        int d = edge_idx(ei, 1, e);
        int p = atomicAdd(&g_pos[d], 1);
        g_srcs[p] = edge_idx(ei, 0, e);
        g_eids[p] = e;
    }
}

// ---------------- layer-1 aggregation (fp16 gather, fp32 acc) ----------------
__global__ void k_agg1() {
    int warp = threadIdx.x >> 5;
    int lane = threadIdx.x & 31;
    int node = blockIdx.x * 8 + warp;
    if (node >= NN) return;
    int beg = g_off[node], end = g_off[node + 1];
    float a0 = 0.f, a1 = 0.f, a2 = 0.f, a3 = 0.f;
    for (int e = beg; e < end; e++) {
        int s = g_srcs[e];
        uint2 v = ((const uint2*)(g_xf + (size_t)s * 128))[lane];
        float2 f0 = __half22float2(*(__half2*)&v.x);
        float2 f1 = __half22float2(*(__half2*)&v.y);
        a0 += f0.x; a1 += f0.y; a2 += f1.x; a3 += f1.y;
    }
    int cnt = end - beg;
    float inv = 1.0f / (float)(cnt > 0 ? cnt : 1);
    uint2 u = make_uint2(pkh(a0 * inv, a1 * inv), pkh(a2 * inv, a3 * inv));
    *(uint2*)(g_a1f + (size_t)node * 128 + lane * 4) = u;
}

// ---------------- fused dual GEMM --------------------------------------------
// Per 128-row block, 512 threads, 1 CTA/SM:
//   Phase A: h = relu([a1|x]@B1 + b1)   -> h tile in smem (swizzled, 64KB)
//   Phase B: [p|q] = h@B2 (+b2 on q)    -> g_pf, g_qf fp16
// Warp tile 32x64 (16 warps: 4m x 4n), BK=32 double-buffered cp.async.
// smem: [0,20480) A stages | [20480,53248) B stages | [53248,118784) h
__global__ void __launch_bounds__(512, 1) k_gemm_fused(
    const float* __restrict__ b1, const float* __restrict__ b2)
{
    constexpr int ASTG = 10240;          // 128 rows x 80B
    constexpr int BSTG = 16384;          // 32 rows x 512B
    constexpr uint32_t BOFF = 20480;
    constexpr uint32_t HOFF = 53248;

    extern __shared__ char smr[];
    uint32_t sm0 = (uint32_t)__cvta_generic_to_shared(smr);
    uint32_t hs  = sm0 + HOFF;

    int tid = threadIdx.x, lane = tid & 31, warp = tid >> 5;
    int wm0 = (warp >> 2) * 32, wn0 = (warp & 3) * 64;
    int row0 = blockIdx.x * 128;

    float acc[2][8][4];
#pragma unroll
    for (int i = 0; i < 2; i++)
#pragma unroll
        for (int j = 0; j < 8; j++)
#pragma unroll
            for (int q = 0; q < 4; q++) acc[i][j][q] = 0.f;

    // ---------------- phase A ----------------
    auto stageA = [&](int ch, int s) {
        // A: 128 rows x 32 k fp16 (80B stride); 512 x 16B chunks, 1/thread
        {
            int row = tid >> 2, c = tid & 3;
            int grow = row0 + row;
            if (grow >= NN) grow = 0;
            int kk = ch * 32 + c * 8;
            const __half* src = (kk < 128)
                ? g_a1f + (size_t)grow * 128 + kk
                : g_xf  + (size_t)grow * 128 + (kk - 128);
            cpa16(sm0 + (uint32_t)(s * ASTG + row * 80 + c * 16), src);
        }
        // B1: 32 k x 256 n fp16 (512B rows, XOR swizzle); 1024 chunks, 2/thread
#pragma unroll
        for (int i = 0; i < 2; i++) {
            int idx = tid + i * 512;
            int k = idx >> 5, c = idx & 31;
            const __half* src = g_B1f + (size_t)(ch * 32 + k) * 256 + c * 8;
            cpa16(sm0 + BOFF + (uint32_t)(s * BSTG + k * 512 + ((c ^ (k & 7)) << 4)), src);
        }
    };

    stageA(0, 0);
    cpa_commit();
    for (int ch = 0; ch < 8; ch++) {
        int s = ch & 1;
        if (ch + 1 < 8) {
            stageA(ch + 1, (ch + 1) & 1);
            cpa_commit();
            cpa_wait<1>();
        } else {
            cpa_wait<0>();
        }
        __syncthreads();
        uint32_t ab = sm0 + (uint32_t)(s * ASTG);
        uint32_t bb = sm0 + BOFF + (uint32_t)(s * BSTG);
#pragma unroll
        for (int ks = 0; ks < 2; ks++) {
            uint32_t aF[2][4];
#pragma unroll
            for (int mt = 0; mt < 2; mt++) {
                int r  = wm0 + mt * 16 + (lane & 15);
                int kc = ks * 16 + ((lane >> 4) << 3);
                ldsm4(aF[mt], ab + (uint32_t)(r * 80 + kc * 2));
            }
#pragma unroll
            for (int nt = 0; nt < 8; nt++) {
                int kk = ks * 16 + (lane & 15);
                int cc = (wn0 + nt * 8) >> 3;
                uint32_t bF[2];
                ldsm2t(bF, bb + (uint32_t)(kk * 512 + ((cc ^ (kk & 7)) << 4)));
#pragma unroll
                for (int mt = 0; mt < 2; mt++)
                    mma_f16(acc[mt][nt], aF[mt], bF);
            }
        }
        __syncthreads();
    }

    // phase A epilogue: bias + relu -> h smem (swizzled, 512B row stride)
#pragma unroll
    for (int mt = 0; mt < 2; mt++) {
        int rl = wm0 + mt * 16 + (lane >> 2);
#pragma unroll
        for (int nt = 0; nt < 8; nt++) {
            int col = wn0 + nt * 8 + (lane & 3) * 2;
            float c0 = b1[col], c1 = b1[col + 1];
#pragma unroll
            for (int half = 0; half < 2; half++) {
                int rr = rl + half * 8;
                float vx = fmaxf(acc[mt][nt][half * 2]     + c0, 0.f);
                float vy = fmaxf(acc[mt][nt][half * 2 + 1] + c1, 0.f);
                uint32_t addr = hs + (uint32_t)(rr * 512 +
                    (((col >> 3) ^ (rr & 7)) << 4) + (col & 7) * 2);
                asm volatile("st.shared.b32 [%0], %1;" :: "r"(addr), "r"(pkh(vx, vy)) : "memory");
            }
        }
    }
#pragma unroll
    for (int i = 0; i < 2; i++)
#pragma unroll
        for (int j = 0; j < 8; j++)
#pragma unroll
            for (int q = 0; q < 4; q++) acc[i][j][q] = 0.f;
    __syncthreads();

    // ---------------- phase B: [p|q] = h @ B2 ----------------
    auto stageB = [&](int ch, int s) {
#pragma unroll
        for (int i = 0; i < 2; i++) {
            int idx = tid + i * 512;
            int k = idx >> 5, c = idx & 31;
            const __half* src = g_B2f + (size_t)(ch * 32 + k) * 256 + c * 8;
            cpa16(sm0 + BOFF + (uint32_t)(s * BSTG + k * 512 + ((c ^ (k & 7)) << 4)), src);
        }
    };

    stageB(0, 0);
    cpa_commit();
    for (int ch = 0; ch < 8; ch++) {
        int s = ch & 1;
        if (ch + 1 < 8) {
            stageB(ch + 1, (ch + 1) & 1);
            cpa_commit();
            cpa_wait<1>();
        } else {
            cpa_wait<0>();
        }
        __syncthreads();
        uint32_t bb = sm0 + BOFF + (uint32_t)(s * BSTG);
#pragma unroll
        for (int ks = 0; ks < 2; ks++) {
            uint32_t aF[2][4];
#pragma unroll
            for (int mt = 0; mt < 2; mt++) {
                int r = wm0 + mt * 16 + (lane & 15);
                int c = ch * 4 + ks * 2 + (lane >> 4);       // 16B chunk in h row
                ldsm4(aF[mt], hs + (uint32_t)(r * 512 + ((c ^ (r & 7)) << 4)));
            }
#pragma unroll
            for (int nt = 0; nt < 8; nt++) {
                int kk = ks * 16 + (lane & 15);
                int cc = (wn0 + nt * 8) >> 3;
                uint32_t bF[2];
                ldsm2t(bF, bb + (uint32_t)(kk * 512 + ((cc ^ (kk & 7)) << 4)));
#pragma unroll
                for (int mt = 0; mt < 2; mt++)
                    mma_f16(acc[mt][nt], aF[mt], bF);
            }
        }
        __syncthreads();
    }

    // phase B epilogue: cols 0-127 -> pf, cols 128-255 (+b2) -> qf
#pragma unroll
    for (int mt = 0; mt < 2; mt++) {
        int rl = wm0 + mt * 16 + (lane >> 2);
#pragma unroll
        for (int nt = 0; nt < 8; nt++) {
            int col = wn0 + nt * 8 + (lane & 3) * 2;
            float c0 = 0.f, c1 = 0.f;
            if (col >= 128) { c0 = b2[col - 128]; c1 = b2[col - 127]; }
#pragma unroll
            for (int half = 0; half < 2; half++) {
                int rr = row0 + rl + half * 8;
                if (rr >= NN) continue;
                float vx = acc[mt][nt][half * 2]     + c0;
                float vy = acc[mt][nt][half * 2 + 1] + c1;
                if (col < 128)
                    *(uint32_t*)(g_pf + (size_t)rr * 128 + col) = pkh(vx, vy);
                else
                    *(uint32_t*)(g_qf + (size_t)rr * 128 + (col - 128)) = pkh(vx, vy);
            }
        }
    }
}

// ---------------- layer-2 finish: refined = mean(p[srcs]) + q ----------------
__global__ void k_agg2f(float* __restrict__ refined) {
    int warp = threadIdx.x >> 5;
    int lane = threadIdx.x & 31;
    int node = blockIdx.x * 8 + warp;
    if (node >= NN) return;
    int beg = g_off[node], end = g_off[node + 1];
    float a0 = 0.f, a1 = 0.f, a2 = 0.f, a3 = 0.f;
    for (int e = beg; e < end; e++) {
        int s = g_srcs[e];
        uint2 v = ((const uint2*)(g_pf + (size_t)s * 128))[lane];
        float2 f0 = __half22float2(*(__half2*)&v.x);
        float2 f1 = __half22float2(*(__half2*)&v.y);
        a0 += f0.x; a1 += f0.y; a2 += f1.x; a3 += f1.y;
    }
    int cnt = end - beg;
    float inv = 1.0f / (float)(cnt > 0 ? cnt : 1);
    uint2 qv = ((const uint2*)(g_qf + (size_t)node * 128))[lane];
    float2 q0 = __half22float2(*(__half2*)&qv.x);
    float2 q1 = __half22float2(*(__half2*)&qv.y);
    float4 o = make_float4(a0 * inv + q0.x, a1 * inv + q0.y,
                           a2 * inv + q1.x, a3 * inv + q1.y);
    ((float4*)(refined + (size_t)node * 128))[lane] = o;
    *(uint2*)(g_rf + (size_t)node * 128 + lane * 4) =
        make_uint2(pkh(o.x, o.y), pkh(o.z, o.w));
}

// ---------------- CSR-order edge scoring -------------------------------------
__global__ void k_score(float* __restrict__ out) {
    int warp = threadIdx.x >> 5;
    int lane = threadIdx.x & 31;
    int node = blockIdx.x * 8 + warp;
    if (node >= NN) return;
    int beg = g_off[node], end = g_off[node + 1];
    if (beg == end) return;
    uint2 va = ((const uint2*)(g_rf + (size_t)node * 128))[lane];
    float2 d0 = __half22float2(*(__half2*)&va.x);
    float2 d1 = __half22float2(*(__half2*)&va.y);
    for (int e = beg; e < end; e++) {
        int s = g_srcs[e];
        uint2 vb = ((const uint2*)(g_rf + (size_t)s * 128))[lane];
        float2 s0 = __half22float2(*(__half2*)&vb.x);
        float2 s1 = __half22float2(*(__half2*)&vb.y);
        float t = d0.x * s0.x + d0.y * s0.y + d1.x * s1.x + d1.y * s1.y;
#pragma unroll
        for (int o = 16; o > 0; o >>= 1) t += __shfl_xor_sync(0xFFFFFFFFu, t, o);
        if (lane == 0) out[g_eids[e]] = t;
    }
}

// ---------------- launch -----------------------------------------------------
extern "C" void kernel_launch(void* const* d_in, const int* in_sizes, int n_in,
                              void* d_out, int out_size)
{
    const void*  ei    = d_in[0];
    const float* movie = (const float*)d_in[2];
    const float* user  = (const float*)d_in[3];
    const float* Wl1   = (const float*)d_in[4];
    const float* bl1   = (const float*)d_in[5];
    const float* Wr1   = (const float*)d_in[6];
    const float* Wl2   = (const float*)d_in[7];
    const float* bl2   = (const float*)d_in[8];
    const float* Wr2   = (const float*)d_in[9];

    float* out     = (float*)d_out;
    float* refined = out + NE;

    const int MB = (NN + 127) / 128;      // 1172
    const int FSMEM = 118784;             // fused GEMM smem
    const int PREP_B = (NN * 128 / 4 + 255) / 256;

    cudaFuncSetAttribute(k_gemm_fused, cudaFuncAttributeMaxDynamicSharedMemorySize, FSMEM);

    k_prep<<<PREP_B, 256>>>(ei, movie, user, Wl1, Wr1, Wl2, Wr2);
    k_count<<<(NE + 255) / 256, 256>>>(ei);
    k_scan1<<<(NN + 1023) / 1024, 1024>>>();
    k_scan2<<<1, 256>>>();
    k_scan3<<<(NN + 255) / 256, 256>>>();
    k_bucket<<<(NE + 255) / 256, 256>>>(ei);
    k_agg1<<<(NN + 7) / 8, 256>>>();
    k_gemm_fused<<<MB, 512, FSMEM>>>(bl1, bl2);
    k_agg2f<<<(NN + 7) / 8, 256>>>(refined);
    k_score<<<(NN + 7) / 8, 256>>>(out);
}